// round 12
// baseline (speedup 1.0000x reference)
#include <cuda_runtime.h>
#include <cuda_fp16.h>
#include <math.h>

#define NN 50000
#define EE 800000
#define ET (EE + NN)
#define GG 64
#define F_IN 128
#define H1DIM 256   // HEADS * HID
#define H2DIM 32
#define NEG_SLOPE 0.2f
#define EB 3321                 // ceil(ET/256)
#define G1B 3128                // gemm1 blocks: 782 row-blocks x 4 col-blocks
#define A1B 6250                // alpha1 blocks: NN*32/256
#define AGG2B 3125              // agg2 blocks

// ---------------- scratch ----------------
__device__ __align__(16) __half g_h1[NN * H1DIM];     // fp16 layer1 features
__device__ __align__(16) __half g_out1h[NN * H1DIM];  // fp16 layer1 output (gemm2 input)
__device__ __align__(16) float g_as1[NN * 4];
__device__ __align__(16) float g_ad1[NN * 4];
__device__ __align__(16) __half g_h2[NN * H2DIM];     // fp16 layer2 features
__device__ float g_as2[NN];
__device__ float g_ad2[NN];
__device__ float g_pool[GG * H2DIM];
__device__ float g_cnt[GG];
__device__ int g_deg[NN];
__device__ int g_cur[NN];
__device__ int g_off[NN + 1];
__device__ int g_csr_src[ET];
__device__ __align__(16) float g_wsd1[F_IN * 8];      // [f][s0..s3,d0..d3]
__device__ __align__(16) __half g_w1h[F_IN * H1DIM];  // fp16 W1
__device__ __align__(16) __half g_w2h[H1DIM * H2DIM]; // fp16 W2
__device__ int g_scan_flag;                           // set by scan body, reset by prep
__device__ int g_done;                                // agg2 last-block counter (zero-init)

// ---------------- helpers ----------------
__device__ __forceinline__ float leaky(float e) {
    return (e >= 0.f) ? e : NEG_SLOPE * e;
}
__device__ __forceinline__ unsigned smem_u32(const void* p) {
    return (unsigned)__cvta_generic_to_shared(p);
}
__device__ __forceinline__ void ldsm_x4(unsigned& r0, unsigned& r1, unsigned& r2, unsigned& r3, unsigned a) {
    asm volatile("ldmatrix.sync.aligned.m8n8.x4.shared.b16 {%0,%1,%2,%3},[%4];"
                 : "=r"(r0), "=r"(r1), "=r"(r2), "=r"(r3) : "r"(a));
}
__device__ __forceinline__ void ldsm_x4t(unsigned& r0, unsigned& r1, unsigned& r2, unsigned& r3, unsigned a) {
    asm volatile("ldmatrix.sync.aligned.m8n8.x4.trans.shared.b16 {%0,%1,%2,%3},[%4];"
                 : "=r"(r0), "=r"(r1), "=r"(r2), "=r"(r3) : "r"(a));
}
__device__ __forceinline__ void mma16816(float* d, const unsigned* a, unsigned b0, unsigned b1) {
    asm volatile("mma.sync.aligned.m16n8k16.row.col.f32.f16.f16.f32 "
                 "{%0,%1,%2,%3},{%4,%5,%6,%7},{%8,%9},{%0,%1,%2,%3};"
                 : "+f"(d[0]), "+f"(d[1]), "+f"(d[2]), "+f"(d[3])
                 : "r"(a[0]), "r"(a[1]), "r"(a[2]), "r"(a[3]), "r"(b0), "r"(b1));
}

// ---------------- K1: prep (4 blocks) + hist (EB blocks) fused ----------------
__global__ void prep_hist_kernel(const int* __restrict__ adj,
                                 const float* __restrict__ W1,
                                 const float* __restrict__ a1s, const float* __restrict__ a1d,
                                 const float* __restrict__ W2) {
    int bx = blockIdx.x;
    int tid = threadIdx.x;
    if (bx < EB) {
        int e = bx * 256 + tid;
        if (e >= ET) return;
        int dst = (e < EE) ? adj[EE + e] : e - EE;
        atomicAdd(&g_deg[dst], 1);
    } else {
        int pt = (bx - EB) * 256 + tid;  // 0..1023
        {
            int f = pt >> 3, o = pt & 7;
            int h = o & 3, sd = o >> 2;
            const float* a = sd ? a1d : a1s;
            float s = 0.f;
#pragma unroll 8
            for (int d = 0; d < 64; d++) s += W1[f * H1DIM + h * 64 + d] * a[h * 64 + d];
            g_wsd1[f * 8 + o] = s;
        }
        for (int j = pt; j < F_IN * H1DIM; j += 1024) g_w1h[j] = __float2half_rn(W1[j]);
        for (int j = pt; j < H1DIM * H2DIM; j += 1024) g_w2h[j] = __float2half_rn(W2[j]);
        for (int j = pt; j < GG * H2DIM; j += 1024) g_pool[j] = 0.f;
        if (pt < GG) g_cnt[pt] = 0.f;
        if (pt == 0) g_scan_flag = 0;
    }
}

// ---------------- scan body: 256-thread serial block scan (block 0 of mid) ----------------
__device__ void scan_body() {
    __shared__ int warpsum[8];
    int tid = threadIdx.x;
    int lane = tid & 31, wid = tid >> 5;
    int running = 0;
    for (int base = 0; base < NN; base += 256) {
        int i = base + tid;
        int v = (i < NN) ? g_deg[i] : 0;
        int val = v;
#pragma unroll
        for (int off = 1; off < 32; off <<= 1) {
            int t = __shfl_up_sync(0xffffffffu, val, off);
            if (lane >= off) val += t;
        }
        if (lane == 31) warpsum[wid] = val;
        __syncthreads();
        if (wid == 0) {
            int s = (lane < 8) ? warpsum[lane] : 0;
#pragma unroll
            for (int off = 1; off < 8; off <<= 1) {
                int t = __shfl_up_sync(0xffffffffu, s, off);
                if (lane >= off) s += t;
            }
            if (lane < 8) warpsum[lane] = s;
        }
        __syncthreads();
        int warpbase = (wid == 0) ? 0 : warpsum[wid - 1];
        int excl = running + warpbase + val - v;
        if (i < NN) { g_off[i] = excl; g_cur[i] = excl; }
        running += warpsum[7];
        __syncthreads();
    }
    if (tid == 0) g_off[NN] = running;
    __syncthreads();
    __threadfence();
    if (tid == 0) atomicExch(&g_scan_flag, 1);
}

// ---------------- scatter body (after spin on scan flag) ----------------
__device__ void scatter_body(int base, const int* __restrict__ adj) {
    int tid = threadIdx.x;
    if (tid == 0) {
        while (atomicAdd(&g_scan_flag, 0) == 0) __nanosleep(64);
    }
    __syncthreads();
    __threadfence();
    int gt = base * 256 + tid;
    const int STR = EB * 256;
    for (int j = gt; j < NN; j += STR) g_deg[j] = 0;   // reset for next replay
    if (gt >= ET) return;
    int src, dst;
    if (gt < EE) { src = adj[gt]; dst = adj[EE + gt]; }
    else         { src = dst = gt - EE; }
    int p = atomicAdd(&g_cur[dst], 1);
    g_csr_src[p] = src;
}

__device__ void alpha1_body(int aid, const float* __restrict__ x) {
    int gt = aid * 256 + threadIdx.x;
    int n = gt >> 5, lane = gt & 31;
    if (n >= NN) return;
    float4 xv = ((const float4*)x)[n * 32 + lane];
    float a0 = 0, a1 = 0, a2 = 0, a3 = 0, b0 = 0, b1 = 0, b2 = 0, b3 = 0;
    float xj[4] = {xv.x, xv.y, xv.z, xv.w};
#pragma unroll
    for (int j = 0; j < 4; j++) {
        int f = lane * 4 + j;
        float4 wa = *(const float4*)&g_wsd1[f * 8];
        float4 wb = *(const float4*)&g_wsd1[f * 8 + 4];
        a0 = fmaf(xj[j], wa.x, a0); a1 = fmaf(xj[j], wa.y, a1);
        a2 = fmaf(xj[j], wa.z, a2); a3 = fmaf(xj[j], wa.w, a3);
        b0 = fmaf(xj[j], wb.x, b0); b1 = fmaf(xj[j], wb.y, b1);
        b2 = fmaf(xj[j], wb.z, b2); b3 = fmaf(xj[j], wb.w, b3);
    }
#pragma unroll
    for (int off = 16; off; off >>= 1) {
        a0 += __shfl_xor_sync(0xffffffffu, a0, off);
        a1 += __shfl_xor_sync(0xffffffffu, a1, off);
        a2 += __shfl_xor_sync(0xffffffffu, a2, off);
        a3 += __shfl_xor_sync(0xffffffffu, a3, off);
        b0 += __shfl_xor_sync(0xffffffffu, b0, off);
        b1 += __shfl_xor_sync(0xffffffffu, b1, off);
        b2 += __shfl_xor_sync(0xffffffffu, b2, off);
        b3 += __shfl_xor_sync(0xffffffffu, b3, off);
    }
    if (lane == 0) {
        *(float4*)&g_as1[n * 4] = make_float4(a0, a1, a2, a3);
        *(float4*)&g_ad1[n * 4] = make_float4(b0, b1, b2, b3);
    }
}

// ---------------- K2: scan + scatter + gemm1(HMMA) + alpha1 ----------------
__global__ __launch_bounds__(256) void mid_kernel(const int* __restrict__ adj,
                                                  const float* __restrict__ x) {
    __shared__ __align__(16) __half As[64][136];
    __shared__ __align__(16) __half Bs[128][72];
    if (blockIdx.x == 0) { scan_body(); return; }
    int bb = blockIdx.x - 1;
    int m = bb & 3, base = bb >> 2;
    if (m == 2) { if (base < EB) scatter_body(base, adj); return; }
    if (m & 1)  { int aid = base * 2 + (m == 3); if (aid < A1B) alpha1_body(aid, x); return; }
    if (base >= G1B) return;
    int tid = threadIdx.x;
    int row0 = (base >> 2) * 64;
    int col0 = (base & 3) * 64;
    for (int i = tid; i < 64 * 32; i += 256) {
        int r = i >> 5, c4 = i & 31;
        int row = row0 + r;
        float4 v = (row < NN) ? *(const float4*)&x[row * F_IN + c4 * 4]
                              : make_float4(0.f, 0.f, 0.f, 0.f);
        *(half2*)&As[r][c4 * 4] = __floats2half2_rn(v.x, v.y);
        *(half2*)&As[r][c4 * 4 + 2] = __floats2half2_rn(v.z, v.w);
    }
    for (int i = tid; i < 128 * 8; i += 256) {
        int r = i >> 3, c8 = i & 7;
        *(uint4*)&Bs[r][c8 * 8] = *(const uint4*)&g_w1h[r * H1DIM + col0 + c8 * 8];
    }
    __syncthreads();
    int wid = tid >> 5, lane = tid & 31;
    int rowg = wid >> 1, colg = wid & 1;
    unsigned a[8][4];
#pragma unroll
    for (int ks = 0; ks < 8; ks++) {
        unsigned addr = smem_u32(&As[rowg * 16 + (lane & 15)][ks * 16 + (lane >> 4) * 8]);
        ldsm_x4(a[ks][0], a[ks][1], a[ks][2], a[ks][3], addr);
    }
    float d[4][4];
#pragma unroll
    for (int nt = 0; nt < 4; nt++)
#pragma unroll
        for (int j = 0; j < 4; j++) d[nt][j] = 0.f;
#pragma unroll
    for (int np = 0; np < 2; np++) {
#pragma unroll
        for (int ks = 0; ks < 8; ks++) {
            unsigned b0, b1, b2, b3;
            unsigned addr = smem_u32(&Bs[ks * 16 + (lane & 15)][colg * 32 + np * 16 + (lane >> 4) * 8]);
            ldsm_x4t(b0, b1, b2, b3, addr);
            mma16816(d[np * 2], a[ks], b0, b1);
            mma16816(d[np * 2 + 1], a[ks], b2, b3);
        }
    }
    int g = lane >> 2, t = lane & 3;
    int r_lo = row0 + rowg * 16 + g;
    int r_hi = r_lo + 8;
#pragma unroll
    for (int nt = 0; nt < 4; nt++) {
        int col = col0 + colg * 32 + nt * 8 + 2 * t;
        if (r_lo < NN) *(half2*)&g_h1[r_lo * H1DIM + col] = __floats2half2_rn(d[nt][0], d[nt][1]);
        if (r_hi < NN) *(half2*)&g_h1[r_hi * H1DIM + col] = __floats2half2_rn(d[nt][2], d[nt][3]);
    }
}

// ---------------- agg1: 32 threads/node, software-pipelined gathers ----------------
__global__ void agg1_kernel(const float* __restrict__ b1) {
    int gt = blockIdx.x * blockDim.x + threadIdx.x;
    int n = gt >> 5;
    if (n >= NN) return;
    int c = gt & 31;
    int head = c >> 3;
    int q = c & 3;
    float adh = g_ad1[n * 4 + head];
    int beg = g_off[n], end = g_off[n + 1];
    half2 acc[4];
#pragma unroll
    for (int j = 0; j < 4; j++) acc[j] = __floats2half2_rn(0.f, 0.f);
    float den = 0.f;
    int nb = (end - beg) >> 2;
    int i = beg;
    if (nb > 0) {
        // prologue: load batch 0
        int s0 = g_csr_src[i], s1 = g_csr_src[i + 1];
        int s2 = g_csr_src[i + 2], s3 = g_csr_src[i + 3];
        int sq = (q == 0) ? s0 : (q == 1) ? s1 : (q == 2) ? s2 : s3;
        float eq = __expf(leaky(g_as1[sq * 4 + head] + adh));
        uint4 P0 = ((const uint4*)(g_h1 + s0 * H1DIM))[c];
        uint4 P1 = ((const uint4*)(g_h1 + s1 * H1DIM))[c];
        uint4 P2 = ((const uint4*)(g_h1 + s2 * H1DIM))[c];
        uint4 P3 = ((const uint4*)(g_h1 + s3 * H1DIM))[c];
        for (int g2 = 1; g2 < nb; g2++) {
            int i2 = i + 4;
            // issue next batch loads
            int t0 = g_csr_src[i2], t1 = g_csr_src[i2 + 1];
            int t2 = g_csr_src[i2 + 2], t3 = g_csr_src[i2 + 3];
            int tq = (q == 0) ? t0 : (q == 1) ? t1 : (q == 2) ? t2 : t3;
            float neq = __expf(leaky(g_as1[tq * 4 + head] + adh));
            uint4 N0 = ((const uint4*)(g_h1 + t0 * H1DIM))[c];
            uint4 N1 = ((const uint4*)(g_h1 + t1 * H1DIM))[c];
            uint4 N2 = ((const uint4*)(g_h1 + t2 * H1DIM))[c];
            uint4 N3 = ((const uint4*)(g_h1 + t3 * H1DIM))[c];
            // consume current batch
            float e0 = __shfl_sync(0xffffffffu, eq, (c & 24) + 0);
            float e1 = __shfl_sync(0xffffffffu, eq, (c & 24) + 1);
            float e2 = __shfl_sync(0xffffffffu, eq, (c & 24) + 2);
            float e3 = __shfl_sync(0xffffffffu, eq, (c & 24) + 3);
            den += (e0 + e1) + (e2 + e3);
            half2 h0 = __float2half2_rn(e0), h1e = __float2half2_rn(e1);
            half2 h2e = __float2half2_rn(e2), h3e = __float2half2_rn(e3);
            acc[0] = __hfma2(h0, *(const half2*)&P0.x, acc[0]);
            acc[1] = __hfma2(h0, *(const half2*)&P0.y, acc[1]);
            acc[2] = __hfma2(h0, *(const half2*)&P0.z, acc[2]);
            acc[3] = __hfma2(h0, *(const half2*)&P0.w, acc[3]);
            acc[0] = __hfma2(h1e, *(const half2*)&P1.x, acc[0]);
            acc[1] = __hfma2(h1e, *(const half2*)&P1.y, acc[1]);
            acc[2] = __hfma2(h1e, *(const half2*)&P1.z, acc[2]);
            acc[3] = __hfma2(h1e, *(const half2*)&P1.w, acc[3]);
            acc[0] = __hfma2(h2e, *(const half2*)&P2.x, acc[0]);
            acc[1] = __hfma2(h2e, *(const half2*)&P2.y, acc[1]);
            acc[2] = __hfma2(h2e, *(const half2*)&P2.z, acc[2]);
            acc[3] = __hfma2(h2e, *(const half2*)&P2.w, acc[3]);
            acc[0] = __hfma2(h3e, *(const half2*)&P3.x, acc[0]);
            acc[1] = __hfma2(h3e, *(const half2*)&P3.y, acc[1]);
            acc[2] = __hfma2(h3e, *(const half2*)&P3.z, acc[2]);
            acc[3] = __hfma2(h3e, *(const half2*)&P3.w, acc[3]);
            // rotate
            eq = neq;
            P0 = N0; P1 = N1; P2 = N2; P3 = N3;
            i = i2;
        }
        // epilogue: consume last pipelined batch
        float e0 = __shfl_sync(0xffffffffu, eq, (c & 24) + 0);
        float e1 = __shfl_sync(0xffffffffu, eq, (c & 24) + 1);
        float e2 = __shfl_sync(0xffffffffu, eq, (c & 24) + 2);
        float e3 = __shfl_sync(0xffffffffu, eq, (c & 24) + 3);
        den += (e0 + e1) + (e2 + e3);
        half2 h0 = __float2half2_rn(e0), h1e = __float2half2_rn(e1);
        half2 h2e = __float2half2_rn(e2), h3e = __float2half2_rn(e3);
        acc[0] = __hfma2(h0, *(const half2*)&P0.x, acc[0]);
        acc[1] = __hfma2(h0, *(const half2*)&P0.y, acc[1]);
        acc[2] = __hfma2(h0, *(const half2*)&P0.z, acc[2]);
        acc[3] = __hfma2(h0, *(const half2*)&P0.w, acc[3]);
        acc[0] = __hfma2(h1e, *(const half2*)&P1.x, acc[0]);
        acc[1] = __hfma2(h1e, *(const half2*)&P1.y, acc[1]);
        acc[2] = __hfma2(h1e, *(const half2*)&P1.z, acc[2]);
        acc[3] = __hfma2(h1e, *(const half2*)&P1.w, acc[3]);
        acc[0] = __hfma2(h2e, *(const half2*)&P2.x, acc[0]);
        acc[1] = __hfma2(h2e, *(const half2*)&P2.y, acc[1]);
        acc[2] = __hfma2(h2e, *(const half2*)&P2.z, acc[2]);
        acc[3] = __hfma2(h2e, *(const half2*)&P2.w, acc[3]);
        acc[0] = __hfma2(h3e, *(const half2*)&P3.x, acc[0]);
        acc[1] = __hfma2(h3e, *(const half2*)&P3.y, acc[1]);
        acc[2] = __hfma2(h3e, *(const half2*)&P3.z, acc[2]);
        acc[3] = __hfma2(h3e, *(const half2*)&P3.w, acc[3]);
        i += 4;
    }
    for (; i < end; i++) {
        int s0 = g_csr_src[i];
        float e0 = __expf(leaky(g_as1[s0 * 4 + head] + adh));
        uint4 p0 = ((const uint4*)(g_h1 + s0 * H1DIM))[c];
        den += e0;
        half2 h0 = __float2half2_rn(e0);
        acc[0] = __hfma2(h0, *(const half2*)&p0.x, acc[0]);
        acc[1] = __hfma2(h0, *(const half2*)&p0.y, acc[1]);
        acc[2] = __hfma2(h0, *(const half2*)&p0.z, acc[2]);
        acc[3] = __hfma2(h0, *(const half2*)&p0.w, acc[3]);
    }
    float inv = __fdividef(1.0f, den);
    float4 ba = ((const float4*)b1)[c * 2];
    float4 bb = ((const float4*)b1)[c * 2 + 1];
    float2 f0 = __half22float2(acc[0]);
    float2 f1 = __half22float2(acc[1]);
    float2 f2 = __half22float2(acc[2]);
    float2 f3 = __half22float2(acc[3]);
    half2 o0 = __floats2half2_rn(fmaxf(fmaf(f0.x, inv, ba.x), 0.f), fmaxf(fmaf(f0.y, inv, ba.y), 0.f));
    half2 o1 = __floats2half2_rn(fmaxf(fmaf(f1.x, inv, ba.z), 0.f), fmaxf(fmaf(f1.y, inv, ba.w), 0.f));
    half2 o2 = __floats2half2_rn(fmaxf(fmaf(f2.x, inv, bb.x), 0.f), fmaxf(fmaf(f2.y, inv, bb.y), 0.f));
    half2 o3 = __floats2half2_rn(fmaxf(fmaf(f3.x, inv, bb.z), 0.f), fmaxf(fmaf(f3.y, inv, bb.w), 0.f));
    uint4 pk;
    pk.x = *(unsigned*)&o0; pk.y = *(unsigned*)&o1; pk.z = *(unsigned*)&o2; pk.w = *(unsigned*)&o3;
    ((uint4*)(g_out1h + n * H1DIM))[c] = pk;
}

// ---------------- GEMM2 (HMMA) + alpha2 ----------------
__global__ __launch_bounds__(256) void gemm2_mma(const float* __restrict__ a2s,
                                                 const float* __restrict__ a2d) {
    __shared__ __align__(16) __half As[128][136];
    __shared__ __align__(16) __half Bs[128][40];
    int tid = threadIdx.x;
    int row0 = blockIdx.x * 128;
    int wid = tid >> 5, lane = tid & 31;
    float d[4][4];
#pragma unroll
    for (int nt = 0; nt < 4; nt++)
#pragma unroll
        for (int j = 0; j < 4; j++) d[nt][j] = 0.f;
    for (int st = 0; st < 2; st++) {
        for (int i = tid; i < 128 * 16; i += 256) {
            int r = i >> 4, c8 = i & 15;
            int row = row0 + r;
            uint4 v = (row < NN) ? *(const uint4*)&g_out1h[row * H1DIM + st * 128 + c8 * 8]
                                 : make_uint4(0u, 0u, 0u, 0u);
            *(uint4*)&As[r][c8 * 8] = v;
        }
        for (int i = tid; i < 128 * 4; i += 256) {
            int r = i >> 2, c8 = i & 3;
            *(uint4*)&Bs[r][c8 * 8] = *(const uint4*)&g_w2h[(st * 128 + r) * H2DIM + c8 * 8];
        }
        __syncthreads();
#pragma unroll
        for (int ks = 0; ks < 8; ks++) {
            unsigned a[4];
            unsigned aaddr = smem_u32(&As[wid * 16 + (lane & 15)][ks * 16 + (lane >> 4) * 8]);
            ldsm_x4(a[0], a[1], a[2], a[3], aaddr);
#pragma unroll
            for (int np = 0; np < 2; np++) {
                unsigned b0, b1, b2, b3;
                unsigned baddr = smem_u32(&Bs[ks * 16 + (lane & 15)][np * 16 + (lane >> 4) * 8]);
                ldsm_x4t(b0, b1, b2, b3, baddr);
                mma16816(d[np * 2], a, b0, b1);
                mma16816(d[np * 2 + 1], a, b2, b3);
            }
        }
        __syncthreads();
    }
    int g = lane >> 2, t = lane & 3;
    int r_lo = row0 + wid * 16 + g;
    int r_hi = r_lo + 8;
    float ps_lo = 0, pd_lo = 0, ps_hi = 0, pd_hi = 0;
#pragma unroll
    for (int nt = 0; nt < 4; nt++) {
        int col = nt * 8 + 2 * t;
        float s0 = a2s[col], s1 = a2s[col + 1];
        float t0 = a2d[col], t1 = a2d[col + 1];
        if (r_lo < NN) *(half2*)&g_h2[r_lo * H2DIM + col] = __floats2half2_rn(d[nt][0], d[nt][1]);
        if (r_hi < NN) *(half2*)&g_h2[r_hi * H2DIM + col] = __floats2half2_rn(d[nt][2], d[nt][3]);
        ps_lo += d[nt][0] * s0 + d[nt][1] * s1;
        pd_lo += d[nt][0] * t0 + d[nt][1] * t1;
        ps_hi += d[nt][2] * s0 + d[nt][3] * s1;
        pd_hi += d[nt][2] * t0 + d[nt][3] * t1;
    }
#pragma unroll
    for (int off = 1; off <= 2; off <<= 1) {
        ps_lo += __shfl_xor_sync(0xffffffffu, ps_lo, off);
        pd_lo += __shfl_xor_sync(0xffffffffu, pd_lo, off);
        ps_hi += __shfl_xor_sync(0xffffffffu, ps_hi, off);
        pd_hi += __shfl_xor_sync(0xffffffffu, pd_hi, off);
    }
    if (t == 0) {
        if (r_lo < NN) { g_as2[r_lo] = ps_lo; g_ad2[r_lo] = pd_lo; }
        if (r_hi < NN) { g_as2[r_hi] = ps_hi; g_ad2[r_hi] = pd_hi; }
    }
}

// ---------------- agg2 + bias + log_softmax + pool + (last block: final) ----------------
__global__ void agg2_lsm_kernel(const float* __restrict__ b2, const int* __restrict__ batch,
                                const float* __restrict__ lin_W, const float* __restrict__ lin_b,
                                float* __restrict__ out) {
    __shared__ int amLast;
    int tid = threadIdx.x;
    int gt = blockIdx.x * blockDim.x + tid;
    int n = gt >> 4;
    if (n < NN) {
        int sub = gt & 15;
        float ad = g_ad2[n];
        int beg = g_off[n], end = g_off[n + 1];
        half2 acc = __floats2half2_rn(0.f, 0.f);
        float den = 0.f;
        int i = beg;
        for (; i + 4 <= end; i += 4) {
            int s0 = g_csr_src[i], s1 = g_csr_src[i + 1];
            int s2 = g_csr_src[i + 2], s3 = g_csr_src[i + 3];
            float e0 = __expf(leaky(g_as2[s0] + ad));
            float e1 = __expf(leaky(g_as2[s1] + ad));
            float e2 = __expf(leaky(g_as2[s2] + ad));
            float e3 = __expf(leaky(g_as2[s3] + ad));
            half2 f0 = ((const half2*)(g_h2 + s0 * H2DIM))[sub];
            half2 f1 = ((const half2*)(g_h2 + s1 * H2DIM))[sub];
            half2 f2 = ((const half2*)(g_h2 + s2 * H2DIM))[sub];
            half2 f3 = ((const half2*)(g_h2 + s3 * H2DIM))[sub];
            den += (e0 + e1) + (e2 + e3);
            acc = __hfma2(__float2half2_rn(e0), f0, acc);
            acc = __hfma2(__float2half2_rn(e1), f1, acc);
            acc = __hfma2(__float2half2_rn(e2), f2, acc);
            acc = __hfma2(__float2half2_rn(e3), f3, acc);
        }
        for (; i < end; i++) {
            int s0 = g_csr_src[i];
            float e0 = __expf(leaky(g_as2[s0] + ad));
            half2 f0 = ((const half2*)(g_h2 + s0 * H2DIM))[sub];
            den += e0;
            acc = __hfma2(__float2half2_rn(e0), f0, acc);
        }
        float2 fa = __half22float2(acc);
        float inv = __fdividef(1.0f, den);
        float v0 = fmaf(fa.x, inv, b2[sub * 2]);
        float v1 = fmaf(fa.y, inv, b2[sub * 2 + 1]);
        float mx = fmaxf(v0, v1);
#pragma unroll
        for (int off = 8; off; off >>= 1) mx = fmaxf(mx, __shfl_xor_sync(0xffffffffu, mx, off));
        float s = expf(v0 - mx) + expf(v1 - mx);
#pragma unroll
        for (int off = 8; off; off >>= 1) s += __shfl_xor_sync(0xffffffffu, s, off);
        float lse = mx + logf(s);
        int b = batch[n];
        atomicAdd(&g_pool[b * H2DIM + sub * 2], v0 - lse);
        atomicAdd(&g_pool[b * H2DIM + sub * 2 + 1], v1 - lse);
        if (sub == 0) atomicAdd(&g_cnt[b], 1.0f);
    }
    // last-block: compute final output
    __syncthreads();
    if (tid == 0) {
        __threadfence();
        int old = atomicAdd(&g_done, 1);
        amLast = (old == gridDim.x - 1) ? 1 : 0;
    }
    __syncthreads();
    if (amLast) {
        __threadfence();
        if (tid < GG) {
            float invc = 1.0f / fmaxf(g_cnt[tid], 1.0f);
            float acc2 = lin_b[0];
#pragma unroll
            for (int j = 0; j < H2DIM; j++) acc2 += g_pool[tid * H2DIM + j] * invc * lin_W[j];
            out[tid] = acc2;
        }
        if (tid == 0) g_done = 0;
    }
}

// ---------------- launcher ----------------
extern "C" void kernel_launch(void* const* d_in, const int* in_sizes, int n_in,
                              void* d_out, int out_size) {
    const float* x      = (const float*)d_in[0];
    const int*   adj    = (const int*)d_in[1];
    const int*   batch  = (const int*)d_in[2];
    const float* W1     = (const float*)d_in[3];
    const float* a1_src = (const float*)d_in[4];
    const float* a1_dst = (const float*)d_in[5];
    const float* b1     = (const float*)d_in[6];
    const float* W2     = (const float*)d_in[7];
    const float* a2_src = (const float*)d_in[8];
    const float* a2_dst = (const float*)d_in[9];
    const float* b2     = (const float*)d_in[10];
    const float* lin_W  = (const float*)d_in[11];
    const float* lin_b  = (const float*)d_in[12];
    float* out = (float*)d_out;

    const int TB = 256;

    prep_hist_kernel<<<EB + 4, TB>>>(adj, W1, a1_src, a1_dst, W2);
    mid_kernel<<<1 + 4 * EB, TB>>>(adj, x);   // scan + scatter + gemm1 + alpha1
    agg1_kernel<<<(NN * 32 + TB - 1) / TB, TB>>>(b1);
    gemm2_mma<<<(NN + 127) / 128, TB>>>(a2_src, a2_dst);
    agg2_lsm_kernel<<<AGG2B, TB>>>(b2, batch, lin_W, lin_b, out);
}

// round 13
// speedup vs baseline: 1.2364x; 1.2364x over previous
#include <cuda_runtime.h>
#include <cuda_fp16.h>
#include <math.h>

#define NN 50000
#define EE 800000
#define ET (EE + NN)
#define GG 64
#define F_IN 128
#define H1DIM 256   // HEADS * HID
#define H2DIM 32
#define NEG_SLOPE 0.2f
#define EB 3321                 // ceil(ET/256)
#define G1B 3128                // gemm1 blocks: 782 row-blocks x 4 col-blocks
#define A1B 6250                // alpha1 blocks: NN*32/256
#define AGG2B 3125              // agg2 blocks

// ---------------- scratch ----------------
__device__ __align__(16) __half g_h1[NN * H1DIM];     // fp16 layer1 features
__device__ __align__(16) __half g_out1h[NN * H1DIM];  // fp16 layer1 output (gemm2 input)
__device__ __align__(16) float g_as1[NN * 4];
__device__ __align__(16) float g_ad1[NN * 4];
__device__ __align__(16) __half g_h2[NN * H2DIM];     // fp16 layer2 features
__device__ float g_as2[NN];
__device__ float g_ad2[NN];
__device__ float g_pool[GG * H2DIM];
__device__ float g_cnt[GG];
__device__ int g_deg[NN];
__device__ int g_cur[NN];
__device__ int g_off[NN + 1];
__device__ int g_csr_src[ET];
__device__ __align__(16) float g_wsd1[F_IN * 8];      // [f][s0..s3,d0..d3]
__device__ __align__(16) __half g_w1h[F_IN * H1DIM];  // fp16 W1
__device__ __align__(16) __half g_w2h[H1DIM * H2DIM]; // fp16 W2
__device__ int g_done;                                // agg2 last-block counter (zero-init)

// ---------------- helpers ----------------
__device__ __forceinline__ float leaky(float e) {
    return (e >= 0.f) ? e : NEG_SLOPE * e;
}
__device__ __forceinline__ unsigned smem_u32(const void* p) {
    return (unsigned)__cvta_generic_to_shared(p);
}
__device__ __forceinline__ void ldsm_x4(unsigned& r0, unsigned& r1, unsigned& r2, unsigned& r3, unsigned a) {
    asm volatile("ldmatrix.sync.aligned.m8n8.x4.shared.b16 {%0,%1,%2,%3},[%4];"
                 : "=r"(r0), "=r"(r1), "=r"(r2), "=r"(r3) : "r"(a));
}
__device__ __forceinline__ void ldsm_x4t(unsigned& r0, unsigned& r1, unsigned& r2, unsigned& r3, unsigned a) {
    asm volatile("ldmatrix.sync.aligned.m8n8.x4.trans.shared.b16 {%0,%1,%2,%3},[%4];"
                 : "=r"(r0), "=r"(r1), "=r"(r2), "=r"(r3) : "r"(a));
}
__device__ __forceinline__ void mma16816(float* d, const unsigned* a, unsigned b0, unsigned b1) {
    asm volatile("mma.sync.aligned.m16n8k16.row.col.f32.f16.f16.f32 "
                 "{%0,%1,%2,%3},{%4,%5,%6,%7},{%8,%9},{%0,%1,%2,%3};"
                 : "+f"(d[0]), "+f"(d[1]), "+f"(d[2]), "+f"(d[3])
                 : "r"(a[0]), "r"(a[1]), "r"(a[2]), "r"(a[3]), "r"(b0), "r"(b1));
}

// ---------------- K1: prep (4 blocks) + hist (EB blocks) fused ----------------
__global__ void prep_hist_kernel(const int* __restrict__ adj,
                                 const float* __restrict__ W1,
                                 const float* __restrict__ a1s, const float* __restrict__ a1d,
                                 const float* __restrict__ W2) {
    int bx = blockIdx.x;
    int tid = threadIdx.x;
    if (bx < EB) {
        int e = bx * 256 + tid;
        if (e >= ET) return;
        int dst = (e < EE) ? adj[EE + e] : e - EE;
        atomicAdd(&g_deg[dst], 1);
    } else {
        int pt = (bx - EB) * 256 + tid;  // 0..1023
        {
            int f = pt >> 3, o = pt & 7;
            int h = o & 3, sd = o >> 2;
            const float* a = sd ? a1d : a1s;
            float s = 0.f;
#pragma unroll 8
            for (int d = 0; d < 64; d++) s += W1[f * H1DIM + h * 64 + d] * a[h * 64 + d];
            g_wsd1[f * 8 + o] = s;
        }
        for (int j = pt; j < F_IN * H1DIM; j += 1024) g_w1h[j] = __float2half_rn(W1[j]);
        for (int j = pt; j < H1DIM * H2DIM; j += 1024) g_w2h[j] = __float2half_rn(W2[j]);
        for (int j = pt; j < GG * H2DIM; j += 1024) g_pool[j] = 0.f;
        if (pt < GG) g_cnt[pt] = 0.f;
    }
}

// ---------------- K2: coalesced block scan (1024 threads) ----------------
__global__ void scan_kernel() {
    __shared__ int warpsum[32];
    int tid = threadIdx.x;
    int lane = tid & 31, wid = tid >> 5;
    int running = 0;
    for (int base = 0; base < NN; base += 1024) {
        int i = base + tid;
        int v = (i < NN) ? g_deg[i] : 0;
        int val = v;
#pragma unroll
        for (int off = 1; off < 32; off <<= 1) {
            int t = __shfl_up_sync(0xffffffffu, val, off);
            if (lane >= off) val += t;
        }
        if (lane == 31) warpsum[wid] = val;
        __syncthreads();
        if (wid == 0) {
            int s = warpsum[lane];
#pragma unroll
            for (int off = 1; off < 32; off <<= 1) {
                int t = __shfl_up_sync(0xffffffffu, s, off);
                if (lane >= off) s += t;
            }
            warpsum[lane] = s;
        }
        __syncthreads();
        int warpbase = (wid == 0) ? 0 : warpsum[wid - 1];
        int excl = running + warpbase + val - v;
        if (i < NN) { g_off[i] = excl; g_cur[i] = excl; }
        running += warpsum[31];
        __syncthreads();
    }
    if (tid == 0) g_off[NN] = running;
}

// ---------------- K3 bodies ----------------
__device__ void scatter_body(int base, const int* __restrict__ adj) {
    int tid = threadIdx.x;
    int gt = base * 256 + tid;
    const int STR = EB * 256;
    for (int j = gt; j < NN; j += STR) g_deg[j] = 0;   // reset for next replay
    if (gt >= ET) return;
    int src, dst;
    if (gt < EE) { src = adj[gt]; dst = adj[EE + gt]; }
    else         { src = dst = gt - EE; }
    int p = atomicAdd(&g_cur[dst], 1);
    g_csr_src[p] = src;
}

__device__ void alpha1_body(int aid, const float* __restrict__ x) {
    int gt = aid * 256 + threadIdx.x;
    int n = gt >> 5, lane = gt & 31;
    if (n >= NN) return;
    float4 xv = ((const float4*)x)[n * 32 + lane];
    float a0 = 0, a1 = 0, a2 = 0, a3 = 0, b0 = 0, b1 = 0, b2 = 0, b3 = 0;
    float xj[4] = {xv.x, xv.y, xv.z, xv.w};
#pragma unroll
    for (int j = 0; j < 4; j++) {
        int f = lane * 4 + j;
        float4 wa = *(const float4*)&g_wsd1[f * 8];
        float4 wb = *(const float4*)&g_wsd1[f * 8 + 4];
        a0 = fmaf(xj[j], wa.x, a0); a1 = fmaf(xj[j], wa.y, a1);
        a2 = fmaf(xj[j], wa.z, a2); a3 = fmaf(xj[j], wa.w, a3);
        b0 = fmaf(xj[j], wb.x, b0); b1 = fmaf(xj[j], wb.y, b1);
        b2 = fmaf(xj[j], wb.z, b2); b3 = fmaf(xj[j], wb.w, b3);
    }
#pragma unroll
    for (int off = 16; off; off >>= 1) {
        a0 += __shfl_xor_sync(0xffffffffu, a0, off);
        a1 += __shfl_xor_sync(0xffffffffu, a1, off);
        a2 += __shfl_xor_sync(0xffffffffu, a2, off);
        a3 += __shfl_xor_sync(0xffffffffu, a3, off);
        b0 += __shfl_xor_sync(0xffffffffu, b0, off);
        b1 += __shfl_xor_sync(0xffffffffu, b1, off);
        b2 += __shfl_xor_sync(0xffffffffu, b2, off);
        b3 += __shfl_xor_sync(0xffffffffu, b3, off);
    }
    if (lane == 0) {
        *(float4*)&g_as1[n * 4] = make_float4(a0, a1, a2, a3);
        *(float4*)&g_ad1[n * 4] = make_float4(b0, b1, b2, b3);
    }
}

// ---------------- K3: scatter + gemm1(HMMA) + alpha1, striped roles ----------------
__global__ __launch_bounds__(256) void mid_kernel(const int* __restrict__ adj,
                                                  const float* __restrict__ x) {
    __shared__ __align__(16) __half As[64][136];
    __shared__ __align__(16) __half Bs[128][72];
    int m = blockIdx.x & 3, base = blockIdx.x >> 2;
    if (m == 2) { if (base < EB) scatter_body(base, adj); return; }
    if (m & 1)  { int aid = base * 2 + (m == 3); if (aid < A1B) alpha1_body(aid, x); return; }
    if (base >= G1B) return;
    int tid = threadIdx.x;
    int row0 = (base >> 2) * 64;
    int col0 = (base & 3) * 64;
    for (int i = tid; i < 64 * 32; i += 256) {
        int r = i >> 5, c4 = i & 31;
        int row = row0 + r;
        float4 v = (row < NN) ? *(const float4*)&x[row * F_IN + c4 * 4]
                              : make_float4(0.f, 0.f, 0.f, 0.f);
        *(half2*)&As[r][c4 * 4] = __floats2half2_rn(v.x, v.y);
        *(half2*)&As[r][c4 * 4 + 2] = __floats2half2_rn(v.z, v.w);
    }
    for (int i = tid; i < 128 * 8; i += 256) {
        int r = i >> 3, c8 = i & 7;
        *(uint4*)&Bs[r][c8 * 8] = *(const uint4*)&g_w1h[r * H1DIM + col0 + c8 * 8];
    }
    __syncthreads();
    int wid = tid >> 5, lane = tid & 31;
    int rowg = wid >> 1, colg = wid & 1;
    unsigned a[8][4];
#pragma unroll
    for (int ks = 0; ks < 8; ks++) {
        unsigned addr = smem_u32(&As[rowg * 16 + (lane & 15)][ks * 16 + (lane >> 4) * 8]);
        ldsm_x4(a[ks][0], a[ks][1], a[ks][2], a[ks][3], addr);
    }
    float d[4][4];
#pragma unroll
    for (int nt = 0; nt < 4; nt++)
#pragma unroll
        for (int j = 0; j < 4; j++) d[nt][j] = 0.f;
#pragma unroll
    for (int np = 0; np < 2; np++) {
#pragma unroll
        for (int ks = 0; ks < 8; ks++) {
            unsigned b0, b1, b2, b3;
            unsigned addr = smem_u32(&Bs[ks * 16 + (lane & 15)][colg * 32 + np * 16 + (lane >> 4) * 8]);
            ldsm_x4t(b0, b1, b2, b3, addr);
            mma16816(d[np * 2], a[ks], b0, b1);
            mma16816(d[np * 2 + 1], a[ks], b2, b3);
        }
    }
    int g = lane >> 2, t = lane & 3;
    int r_lo = row0 + rowg * 16 + g;
    int r_hi = r_lo + 8;
#pragma unroll
    for (int nt = 0; nt < 4; nt++) {
        int col = col0 + colg * 32 + nt * 8 + 2 * t;
        if (r_lo < NN) *(half2*)&g_h1[r_lo * H1DIM + col] = __floats2half2_rn(d[nt][0], d[nt][1]);
        if (r_hi < NN) *(half2*)&g_h1[r_hi * H1DIM + col] = __floats2half2_rn(d[nt][2], d[nt][3]);
    }
}

// ---------------- agg1: 32 threads/node, software-pipelined gathers ----------------
__global__ void agg1_kernel(const float* __restrict__ b1) {
    int gt = blockIdx.x * blockDim.x + threadIdx.x;
    int n = gt >> 5;
    if (n >= NN) return;
    int c = gt & 31;
    int head = c >> 3;
    int q = c & 3;
    float adh = g_ad1[n * 4 + head];
    int beg = g_off[n], end = g_off[n + 1];
    half2 acc[4];
#pragma unroll
    for (int j = 0; j < 4; j++) acc[j] = __floats2half2_rn(0.f, 0.f);
    float den = 0.f;
    int nb = (end - beg) >> 2;
    int i = beg;
    if (nb > 0) {
        int s0 = g_csr_src[i], s1 = g_csr_src[i + 1];
        int s2 = g_csr_src[i + 2], s3 = g_csr_src[i + 3];
        int sq = (q == 0) ? s0 : (q == 1) ? s1 : (q == 2) ? s2 : s3;
        float eq = __expf(leaky(g_as1[sq * 4 + head] + adh));
        uint4 P0 = ((const uint4*)(g_h1 + s0 * H1DIM))[c];
        uint4 P1 = ((const uint4*)(g_h1 + s1 * H1DIM))[c];
        uint4 P2 = ((const uint4*)(g_h1 + s2 * H1DIM))[c];
        uint4 P3 = ((const uint4*)(g_h1 + s3 * H1DIM))[c];
        for (int g2 = 1; g2 < nb; g2++) {
            int i2 = i + 4;
            int t0 = g_csr_src[i2], t1 = g_csr_src[i2 + 1];
            int t2 = g_csr_src[i2 + 2], t3 = g_csr_src[i2 + 3];
            int tq = (q == 0) ? t0 : (q == 1) ? t1 : (q == 2) ? t2 : t3;
            float neq = __expf(leaky(g_as1[tq * 4 + head] + adh));
            uint4 N0 = ((const uint4*)(g_h1 + t0 * H1DIM))[c];
            uint4 N1 = ((const uint4*)(g_h1 + t1 * H1DIM))[c];
            uint4 N2 = ((const uint4*)(g_h1 + t2 * H1DIM))[c];
            uint4 N3 = ((const uint4*)(g_h1 + t3 * H1DIM))[c];
            float e0 = __shfl_sync(0xffffffffu, eq, (c & 24) + 0);
            float e1 = __shfl_sync(0xffffffffu, eq, (c & 24) + 1);
            float e2 = __shfl_sync(0xffffffffu, eq, (c & 24) + 2);
            float e3 = __shfl_sync(0xffffffffu, eq, (c & 24) + 3);
            den += (e0 + e1) + (e2 + e3);
            half2 h0 = __float2half2_rn(e0), h1e = __float2half2_rn(e1);
            half2 h2e = __float2half2_rn(e2), h3e = __float2half2_rn(e3);
            acc[0] = __hfma2(h0, *(const half2*)&P0.x, acc[0]);
            acc[1] = __hfma2(h0, *(const half2*)&P0.y, acc[1]);
            acc[2] = __hfma2(h0, *(const half2*)&P0.z, acc[2]);
            acc[3] = __hfma2(h0, *(const half2*)&P0.w, acc[3]);
            acc[0] = __hfma2(h1e, *(const half2*)&P1.x, acc[0]);
            acc[1] = __hfma2(h1e, *(const half2*)&P1.y, acc[1]);
            acc[2] = __hfma2(h1e, *(const half2*)&P1.z, acc[2]);
            acc[3] = __hfma2(h1e, *(const half2*)&P1.w, acc[3]);
            acc[0] = __hfma2(h2e, *(const half2*)&P2.x, acc[0]);
            acc[1] = __hfma2(h2e, *(const half2*)&P2.y, acc[1]);
            acc[2] = __hfma2(h2e, *(const half2*)&P2.z, acc[2]);
            acc[3] = __hfma2(h2e, *(const half2*)&P2.w, acc[3]);
            acc[0] = __hfma2(h3e, *(const half2*)&P3.x, acc[0]);
            acc[1] = __hfma2(h3e, *(const half2*)&P3.y, acc[1]);
            acc[2] = __hfma2(h3e, *(const half2*)&P3.z, acc[2]);
            acc[3] = __hfma2(h3e, *(const half2*)&P3.w, acc[3]);
            eq = neq;
            P0 = N0; P1 = N1; P2 = N2; P3 = N3;
            i = i2;
        }
        float e0 = __shfl_sync(0xffffffffu, eq, (c & 24) + 0);
        float e1 = __shfl_sync(0xffffffffu, eq, (c & 24) + 1);
        float e2 = __shfl_sync(0xffffffffu, eq, (c & 24) + 2);
        float e3 = __shfl_sync(0xffffffffu, eq, (c & 24) + 3);
        den += (e0 + e1) + (e2 + e3);
        half2 h0 = __float2half2_rn(e0), h1e = __float2half2_rn(e1);
        half2 h2e = __float2half2_rn(e2), h3e = __float2half2_rn(e3);
        acc[0] = __hfma2(h0, *(const half2*)&P0.x, acc[0]);
        acc[1] = __hfma2(h0, *(const half2*)&P0.y, acc[1]);
        acc[2] = __hfma2(h0, *(const half2*)&P0.z, acc[2]);
        acc[3] = __hfma2(h0, *(const half2*)&P0.w, acc[3]);
        acc[0] = __hfma2(h1e, *(const half2*)&P1.x, acc[0]);
        acc[1] = __hfma2(h1e, *(const half2*)&P1.y, acc[1]);
        acc[2] = __hfma2(h1e, *(const half2*)&P1.z, acc[2]);
        acc[3] = __hfma2(h1e, *(const half2*)&P1.w, acc[3]);
        acc[0] = __hfma2(h2e, *(const half2*)&P2.x, acc[0]);
        acc[1] = __hfma2(h2e, *(const half2*)&P2.y, acc[1]);
        acc[2] = __hfma2(h2e, *(const half2*)&P2.z, acc[2]);
        acc[3] = __hfma2(h2e, *(const half2*)&P2.w, acc[3]);
        acc[0] = __hfma2(h3e, *(const half2*)&P3.x, acc[0]);
        acc[1] = __hfma2(h3e, *(const half2*)&P3.y, acc[1]);
        acc[2] = __hfma2(h3e, *(const half2*)&P3.z, acc[2]);
        acc[3] = __hfma2(h3e, *(const half2*)&P3.w, acc[3]);
        i += 4;
    }
    for (; i < end; i++) {
        int s0 = g_csr_src[i];
        float e0 = __expf(leaky(g_as1[s0 * 4 + head] + adh));
        uint4 p0 = ((const uint4*)(g_h1 + s0 * H1DIM))[c];
        den += e0;
        half2 h0 = __float2half2_rn(e0);
        acc[0] = __hfma2(h0, *(const half2*)&p0.x, acc[0]);
        acc[1] = __hfma2(h0, *(const half2*)&p0.y, acc[1]);
        acc[2] = __hfma2(h0, *(const half2*)&p0.z, acc[2]);
        acc[3] = __hfma2(h0, *(const half2*)&p0.w, acc[3]);
    }
    float inv = __fdividef(1.0f, den);
    float4 ba = ((const float4*)b1)[c * 2];
    float4 bb = ((const float4*)b1)[c * 2 + 1];
    float2 f0 = __half22float2(acc[0]);
    float2 f1 = __half22float2(acc[1]);
    float2 f2 = __half22float2(acc[2]);
    float2 f3 = __half22float2(acc[3]);
    half2 o0 = __floats2half2_rn(fmaxf(fmaf(f0.x, inv, ba.x), 0.f), fmaxf(fmaf(f0.y, inv, ba.y), 0.f));
    half2 o1 = __floats2half2_rn(fmaxf(fmaf(f1.x, inv, ba.z), 0.f), fmaxf(fmaf(f1.y, inv, ba.w), 0.f));
    half2 o2 = __floats2half2_rn(fmaxf(fmaf(f2.x, inv, bb.x), 0.f), fmaxf(fmaf(f2.y, inv, bb.y), 0.f));
    half2 o3 = __floats2half2_rn(fmaxf(fmaf(f3.x, inv, bb.z), 0.f), fmaxf(fmaf(f3.y, inv, bb.w), 0.f));
    uint4 pk;
    pk.x = *(unsigned*)&o0; pk.y = *(unsigned*)&o1; pk.z = *(unsigned*)&o2; pk.w = *(unsigned*)&o3;
    ((uint4*)(g_out1h + n * H1DIM))[c] = pk;
}

// ---------------- GEMM2 (HMMA) + alpha2 ----------------
__global__ __launch_bounds__(256) void gemm2_mma(const float* __restrict__ a2s,
                                                 const float* __restrict__ a2d) {
    __shared__ __align__(16) __half As[128][136];
    __shared__ __align__(16) __half Bs[128][40];
    int tid = threadIdx.x;
    int row0 = blockIdx.x * 128;
    int wid = tid >> 5, lane = tid & 31;
    float d[4][4];
#pragma unroll
    for (int nt = 0; nt < 4; nt++)
#pragma unroll
        for (int j = 0; j < 4; j++) d[nt][j] = 0.f;
    for (int st = 0; st < 2; st++) {
        for (int i = tid; i < 128 * 16; i += 256) {
            int r = i >> 4, c8 = i & 15;
            int row = row0 + r;
            uint4 v = (row < NN) ? *(const uint4*)&g_out1h[row * H1DIM + st * 128 + c8 * 8]
                                 : make_uint4(0u, 0u, 0u, 0u);
            *(uint4*)&As[r][c8 * 8] = v;
        }
        for (int i = tid; i < 128 * 4; i += 256) {
            int r = i >> 2, c8 = i & 3;
            *(uint4*)&Bs[r][c8 * 8] = *(const uint4*)&g_w2h[(st * 128 + r) * H2DIM + c8 * 8];
        }
        __syncthreads();
#pragma unroll
        for (int ks = 0; ks < 8; ks++) {
            unsigned a[4];
            unsigned aaddr = smem_u32(&As[wid * 16 + (lane & 15)][ks * 16 + (lane >> 4) * 8]);
            ldsm_x4(a[0], a[1], a[2], a[3], aaddr);
#pragma unroll
            for (int np = 0; np < 2; np++) {
                unsigned b0, b1, b2, b3;
                unsigned baddr = smem_u32(&Bs[ks * 16 + (lane & 15)][np * 16 + (lane >> 4) * 8]);
                ldsm_x4t(b0, b1, b2, b3, baddr);
                mma16816(d[np * 2], a, b0, b1);
                mma16816(d[np * 2 + 1], a, b2, b3);
            }
        }
        __syncthreads();
    }
    int g = lane >> 2, t = lane & 3;
    int r_lo = row0 + wid * 16 + g;
    int r_hi = r_lo + 8;
    float ps_lo = 0, pd_lo = 0, ps_hi = 0, pd_hi = 0;
#pragma unroll
    for (int nt = 0; nt < 4; nt++) {
        int col = nt * 8 + 2 * t;
        float s0 = a2s[col], s1 = a2s[col + 1];
        float t0 = a2d[col], t1 = a2d[col + 1];
        if (r_lo < NN) *(half2*)&g_h2[r_lo * H2DIM + col] = __floats2half2_rn(d[nt][0], d[nt][1]);
        if (r_hi < NN) *(half2*)&g_h2[r_hi * H2DIM + col] = __floats2half2_rn(d[nt][2], d[nt][3]);
        ps_lo += d[nt][0] * s0 + d[nt][1] * s1;
        pd_lo += d[nt][0] * t0 + d[nt][1] * t1;
        ps_hi += d[nt][2] * s0 + d[nt][3] * s1;
        pd_hi += d[nt][2] * t0 + d[nt][3] * t1;
    }
#pragma unroll
    for (int off = 1; off <= 2; off <<= 1) {
        ps_lo += __shfl_xor_sync(0xffffffffu, ps_lo, off);
        pd_lo += __shfl_xor_sync(0xffffffffu, pd_lo, off);
        ps_hi += __shfl_xor_sync(0xffffffffu, ps_hi, off);
        pd_hi += __shfl_xor_sync(0xffffffffu, pd_hi, off);
    }
    if (t == 0) {
        if (r_lo < NN) { g_as2[r_lo] = ps_lo; g_ad2[r_lo] = pd_lo; }
        if (r_hi < NN) { g_as2[r_hi] = ps_hi; g_ad2[r_hi] = pd_hi; }
    }
}

// ---------------- agg2 + bias + log_softmax + pool + (last block: final) ----------------
__global__ void agg2_lsm_kernel(const float* __restrict__ b2, const int* __restrict__ batch,
                                const float* __restrict__ lin_W, const float* __restrict__ lin_b,
                                float* __restrict__ out) {
    __shared__ int amLast;
    int tid = threadIdx.x;
    int gt = blockIdx.x * blockDim.x + tid;
    int n = gt >> 4;
    if (n < NN) {
        int sub = gt & 15;
        float ad = g_ad2[n];
        int beg = g_off[n], end = g_off[n + 1];
        half2 acc = __floats2half2_rn(0.f, 0.f);
        float den = 0.f;
        int i = beg;
        for (; i + 4 <= end; i += 4) {
            int s0 = g_csr_src[i], s1 = g_csr_src[i + 1];
            int s2 = g_csr_src[i + 2], s3 = g_csr_src[i + 3];
            float e0 = __expf(leaky(g_as2[s0] + ad));
            float e1 = __expf(leaky(g_as2[s1] + ad));
            float e2 = __expf(leaky(g_as2[s2] + ad));
            float e3 = __expf(leaky(g_as2[s3] + ad));
            half2 f0 = ((const half2*)(g_h2 + s0 * H2DIM))[sub];
            half2 f1 = ((const half2*)(g_h2 + s1 * H2DIM))[sub];
            half2 f2 = ((const half2*)(g_h2 + s2 * H2DIM))[sub];
            half2 f3 = ((const half2*)(g_h2 + s3 * H2DIM))[sub];
            den += (e0 + e1) + (e2 + e3);
            acc = __hfma2(__float2half2_rn(e0), f0, acc);
            acc = __hfma2(__float2half2_rn(e1), f1, acc);
            acc = __hfma2(__float2half2_rn(e2), f2, acc);
            acc = __hfma2(__float2half2_rn(e3), f3, acc);
        }
        for (; i < end; i++) {
            int s0 = g_csr_src[i];
            float e0 = __expf(leaky(g_as2[s0] + ad));
            half2 f0 = ((const half2*)(g_h2 + s0 * H2DIM))[sub];
            den += e0;
            acc = __hfma2(__float2half2_rn(e0), f0, acc);
        }
        float2 fa = __half22float2(acc);
        float inv = __fdividef(1.0f, den);
        float v0 = fmaf(fa.x, inv, b2[sub * 2]);
        float v1 = fmaf(fa.y, inv, b2[sub * 2 + 1]);
        float mx = fmaxf(v0, v1);
#pragma unroll
        for (int off = 8; off; off >>= 1) mx = fmaxf(mx, __shfl_xor_sync(0xffffffffu, mx, off));
        float s = expf(v0 - mx) + expf(v1 - mx);
#pragma unroll
        for (int off = 8; off; off >>= 1) s += __shfl_xor_sync(0xffffffffu, s, off);
        float lse = mx + logf(s);
        int b = batch[n];
        atomicAdd(&g_pool[b * H2DIM + sub * 2], v0 - lse);
        atomicAdd(&g_pool[b * H2DIM + sub * 2 + 1], v1 - lse);
        if (sub == 0) atomicAdd(&g_cnt[b], 1.0f);
    }
    __syncthreads();
    if (tid == 0) {
        __threadfence();
        int old = atomicAdd(&g_done, 1);
        amLast = (old == gridDim.x - 1) ? 1 : 0;
    }
    __syncthreads();
    if (amLast) {
        __threadfence();
        if (tid < GG) {
            float invc = 1.0f / fmaxf(g_cnt[tid], 1.0f);
            float acc2 = lin_b[0];
#pragma unroll
            for (int j = 0; j < H2DIM; j++) acc2 += g_pool[tid * H2DIM + j] * invc * lin_W[j];
            out[tid] = acc2;
        }
        if (tid == 0) g_done = 0;
    }
}

// ---------------- launcher ----------------
extern "C" void kernel_launch(void* const* d_in, const int* in_sizes, int n_in,
                              void* d_out, int out_size) {
    const float* x      = (const float*)d_in[0];
    const int*   adj    = (const int*)d_in[1];
    const int*   batch  = (const int*)d_in[2];
    const float* W1     = (const float*)d_in[3];
    const float* a1_src = (const float*)d_in[4];
    const float* a1_dst = (const float*)d_in[5];
    const float* b1     = (const float*)d_in[6];
    const float* W2     = (const float*)d_in[7];
    const float* a2_src = (const float*)d_in[8];
    const float* a2_dst = (const float*)d_in[9];
    const float* b2     = (const float*)d_in[10];
    const float* lin_W  = (const float*)d_in[11];
    const float* lin_b  = (const float*)d_in[12];
    float* out = (float*)d_out;

    const int TB = 256;

    prep_hist_kernel<<<EB + 4, TB>>>(adj, W1, a1_src, a1_dst, W2);
    scan_kernel<<<1, 1024>>>();
    mid_kernel<<<4 * EB, TB>>>(adj, x);   // scatter + gemm1 + alpha1 striped
    agg1_kernel<<<(NN * 32 + TB - 1) / TB, TB>>>(b1);
    gemm2_mma<<<(NN + 127) / 128, TB>>>(a2_src, a2_dst);
    agg2_lsm_kernel<<<AGG2B, TB>>>(b2, batch, lin_W, lin_b, out);
}

// round 14
// speedup vs baseline: 1.2619x; 1.0206x over previous
#include <cuda_runtime.h>
#include <cuda_fp16.h>
#include <math.h>

#define NN 50000
#define EE 800000
#define ET (EE + NN)
#define GG 64
#define F_IN 128
#define H1DIM 256   // HEADS * HID
#define H2DIM 32
#define NEG_SLOPE 0.2f
#define EB 3321                 // ceil(ET/256)
#define G1B 3128                // gemm1 blocks: 782 row-blocks x 4 col-blocks
#define A1B 6250                // alpha1 blocks: NN*32/256
#define AGG2B 3125              // agg2 blocks

// ---------------- scratch ----------------
__device__ __align__(16) __half g_h1[NN * H1DIM];     // fp16 layer1 features
__device__ __align__(16) __half g_out1h[NN * H1DIM];  // fp16 layer1 output (gemm2 input)
__device__ __align__(16) float g_as1[NN * 4];
__device__ __align__(16) float g_ad1[NN * 4];
__device__ __align__(16) __half g_h2[NN * H2DIM];     // fp16 layer2 features
__device__ float g_as2[NN];
__device__ float g_ad2[NN];
__device__ float g_pool[GG * H2DIM];
__device__ float g_cnt[GG];
__device__ int g_deg[NN];
__device__ int g_cur[NN];
__device__ int g_off[NN + 1];
__device__ int g_csr_src[ET];
__device__ __align__(16) float g_wsd1[F_IN * 8];      // [f][s0..s3,d0..d3]
__device__ __align__(16) __half g_w1h[F_IN * H1DIM];  // fp16 W1
__device__ __align__(16) __half g_w2h[H1DIM * H2DIM]; // fp16 W2
__device__ int g_done;                                // agg2 last-block counter (zero-init)

// ---------------- helpers ----------------
__device__ __forceinline__ float leaky(float e) {
    return (e >= 0.f) ? e : NEG_SLOPE * e;
}
__device__ __forceinline__ unsigned smem_u32(const void* p) {
    return (unsigned)__cvta_generic_to_shared(p);
}
__device__ __forceinline__ void ldsm_x4(unsigned& r0, unsigned& r1, unsigned& r2, unsigned& r3, unsigned a) {
    asm volatile("ldmatrix.sync.aligned.m8n8.x4.shared.b16 {%0,%1,%2,%3},[%4];"
                 : "=r"(r0), "=r"(r1), "=r"(r2), "=r"(r3) : "r"(a));
}
__device__ __forceinline__ void ldsm_x4t(unsigned& r0, unsigned& r1, unsigned& r2, unsigned& r3, unsigned a) {
    asm volatile("ldmatrix.sync.aligned.m8n8.x4.trans.shared.b16 {%0,%1,%2,%3},[%4];"
                 : "=r"(r0), "=r"(r1), "=r"(r2), "=r"(r3) : "r"(a));
}
__device__ __forceinline__ void mma16816(float* d, const unsigned* a, unsigned b0, unsigned b1) {
    asm volatile("mma.sync.aligned.m16n8k16.row.col.f32.f16.f16.f32 "
                 "{%0,%1,%2,%3},{%4,%5,%6,%7},{%8,%9},{%0,%1,%2,%3};"
                 : "+f"(d[0]), "+f"(d[1]), "+f"(d[2]), "+f"(d[3])
                 : "r"(a[0]), "r"(a[1]), "r"(a[2]), "r"(a[3]), "r"(b0), "r"(b1));
}

// ---------------- K1: prep (4 blocks) + hist (EB blocks) fused ----------------
__global__ void prep_hist_kernel(const int* __restrict__ adj,
                                 const float* __restrict__ W1,
                                 const float* __restrict__ a1s, const float* __restrict__ a1d,
                                 const float* __restrict__ W2) {
    int bx = blockIdx.x;
    int tid = threadIdx.x;
    if (bx < EB) {
        int e = bx * 256 + tid;
        if (e >= ET) return;
        int dst = (e < EE) ? adj[EE + e] : e - EE;
        atomicAdd(&g_deg[dst], 1);
    } else {
        int pt = (bx - EB) * 256 + tid;  // 0..1023
        {
            int f = pt >> 3, o = pt & 7;
            int h = o & 3, sd = o >> 2;
            const float* a = sd ? a1d : a1s;
            float s = 0.f;
#pragma unroll 8
            for (int d = 0; d < 64; d++) s += W1[f * H1DIM + h * 64 + d] * a[h * 64 + d];
            g_wsd1[f * 8 + o] = s;
        }
        for (int j = pt; j < F_IN * H1DIM; j += 1024) g_w1h[j] = __float2half_rn(W1[j]);
        for (int j = pt; j < H1DIM * H2DIM; j += 1024) g_w2h[j] = __float2half_rn(W2[j]);
        for (int j = pt; j < GG * H2DIM; j += 1024) g_pool[j] = 0.f;
        if (pt < GG) g_cnt[pt] = 0.f;
    }
}

// ---------------- K2: coalesced block scan (1024 threads) ----------------
__global__ void scan_kernel() {
    __shared__ int warpsum[32];
    int tid = threadIdx.x;
    int lane = tid & 31, wid = tid >> 5;
    int running = 0;
    for (int base = 0; base < NN; base += 1024) {
        int i = base + tid;
        int v = (i < NN) ? g_deg[i] : 0;
        int val = v;
#pragma unroll
        for (int off = 1; off < 32; off <<= 1) {
            int t = __shfl_up_sync(0xffffffffu, val, off);
            if (lane >= off) val += t;
        }
        if (lane == 31) warpsum[wid] = val;
        __syncthreads();
        if (wid == 0) {
            int s = warpsum[lane];
#pragma unroll
            for (int off = 1; off < 32; off <<= 1) {
                int t = __shfl_up_sync(0xffffffffu, s, off);
                if (lane >= off) s += t;
            }
            warpsum[lane] = s;
        }
        __syncthreads();
        int warpbase = (wid == 0) ? 0 : warpsum[wid - 1];
        int excl = running + warpbase + val - v;
        if (i < NN) { g_off[i] = excl; g_cur[i] = excl; }
        running += warpsum[31];
        __syncthreads();
    }
    if (tid == 0) g_off[NN] = running;
}

// ---------------- K3 bodies ----------------
__device__ void scatter_body(int base, const int* __restrict__ adj) {
    int tid = threadIdx.x;
    int gt = base * 256 + tid;
    const int STR = EB * 256;
    for (int j = gt; j < NN; j += STR) g_deg[j] = 0;   // reset for next replay
    if (gt >= ET) return;
    int src, dst;
    if (gt < EE) { src = adj[gt]; dst = adj[EE + gt]; }
    else         { src = dst = gt - EE; }
    int p = atomicAdd(&g_cur[dst], 1);
    g_csr_src[p] = src;
}

__device__ void alpha1_body(int aid, const float* __restrict__ x) {
    int gt = aid * 256 + threadIdx.x;
    int n = gt >> 5, lane = gt & 31;
    if (n >= NN) return;
    float4 xv = ((const float4*)x)[n * 32 + lane];
    float a0 = 0, a1 = 0, a2 = 0, a3 = 0, b0 = 0, b1 = 0, b2 = 0, b3 = 0;
    float xj[4] = {xv.x, xv.y, xv.z, xv.w};
#pragma unroll
    for (int j = 0; j < 4; j++) {
        int f = lane * 4 + j;
        float4 wa = *(const float4*)&g_wsd1[f * 8];
        float4 wb = *(const float4*)&g_wsd1[f * 8 + 4];
        a0 = fmaf(xj[j], wa.x, a0); a1 = fmaf(xj[j], wa.y, a1);
        a2 = fmaf(xj[j], wa.z, a2); a3 = fmaf(xj[j], wa.w, a3);
        b0 = fmaf(xj[j], wb.x, b0); b1 = fmaf(xj[j], wb.y, b1);
        b2 = fmaf(xj[j], wb.z, b2); b3 = fmaf(xj[j], wb.w, b3);
    }
#pragma unroll
    for (int off = 16; off; off >>= 1) {
        a0 += __shfl_xor_sync(0xffffffffu, a0, off);
        a1 += __shfl_xor_sync(0xffffffffu, a1, off);
        a2 += __shfl_xor_sync(0xffffffffu, a2, off);
        a3 += __shfl_xor_sync(0xffffffffu, a3, off);
        b0 += __shfl_xor_sync(0xffffffffu, b0, off);
        b1 += __shfl_xor_sync(0xffffffffu, b1, off);
        b2 += __shfl_xor_sync(0xffffffffu, b2, off);
        b3 += __shfl_xor_sync(0xffffffffu, b3, off);
    }
    if (lane == 0) {
        *(float4*)&g_as1[n * 4] = make_float4(a0, a1, a2, a3);
        *(float4*)&g_ad1[n * 4] = make_float4(b0, b1, b2, b3);
    }
}

// ---------------- K3: scatter + gemm1(HMMA) + alpha1, striped roles ----------------
__global__ __launch_bounds__(256) void mid_kernel(const int* __restrict__ adj,
                                                  const float* __restrict__ x) {
    __shared__ __align__(16) __half As[64][136];
    __shared__ __align__(16) __half Bs[128][72];
    int m = blockIdx.x & 3, base = blockIdx.x >> 2;
    if (m == 2) { if (base < EB) scatter_body(base, adj); return; }
    if (m & 1)  { int aid = base * 2 + (m == 3); if (aid < A1B) alpha1_body(aid, x); return; }
    if (base >= G1B) return;
    int tid = threadIdx.x;
    int row0 = (base >> 2) * 64;
    int col0 = (base & 3) * 64;
    for (int i = tid; i < 64 * 32; i += 256) {
        int r = i >> 5, c4 = i & 31;
        int row = row0 + r;
        float4 v = (row < NN) ? *(const float4*)&x[row * F_IN + c4 * 4]
                              : make_float4(0.f, 0.f, 0.f, 0.f);
        *(half2*)&As[r][c4 * 4] = __floats2half2_rn(v.x, v.y);
        *(half2*)&As[r][c4 * 4 + 2] = __floats2half2_rn(v.z, v.w);
    }
    for (int i = tid; i < 128 * 8; i += 256) {
        int r = i >> 3, c8 = i & 7;
        *(uint4*)&Bs[r][c8 * 8] = *(const uint4*)&g_w1h[r * H1DIM + col0 + c8 * 8];
    }
    __syncthreads();
    int wid = tid >> 5, lane = tid & 31;
    int rowg = wid >> 1, colg = wid & 1;
    unsigned a[8][4];
#pragma unroll
    for (int ks = 0; ks < 8; ks++) {
        unsigned addr = smem_u32(&As[rowg * 16 + (lane & 15)][ks * 16 + (lane >> 4) * 8]);
        ldsm_x4(a[ks][0], a[ks][1], a[ks][2], a[ks][3], addr);
    }
    float d[4][4];
#pragma unroll
    for (int nt = 0; nt < 4; nt++)
#pragma unroll
        for (int j = 0; j < 4; j++) d[nt][j] = 0.f;
#pragma unroll
    for (int np = 0; np < 2; np++) {
#pragma unroll
        for (int ks = 0; ks < 8; ks++) {
            unsigned b0, b1, b2, b3;
            unsigned addr = smem_u32(&Bs[ks * 16 + (lane & 15)][colg * 32 + np * 16 + (lane >> 4) * 8]);
            ldsm_x4t(b0, b1, b2, b3, addr);
            mma16816(d[np * 2], a[ks], b0, b1);
            mma16816(d[np * 2 + 1], a[ks], b2, b3);
        }
    }
    int g = lane >> 2, t = lane & 3;
    int r_lo = row0 + rowg * 16 + g;
    int r_hi = r_lo + 8;
#pragma unroll
    for (int nt = 0; nt < 4; nt++) {
        int col = col0 + colg * 32 + nt * 8 + 2 * t;
        if (r_lo < NN) *(half2*)&g_h1[r_lo * H1DIM + col] = __floats2half2_rn(d[nt][0], d[nt][1]);
        if (r_hi < NN) *(half2*)&g_h1[r_hi * H1DIM + col] = __floats2half2_rn(d[nt][2], d[nt][3]);
    }
}

// ---------------- agg1: 32 threads/node, shuffle-split exp, HFMA2 accumulation (R11 body) ----------------
__global__ void agg1_kernel(const float* __restrict__ b1) {
    int gt = blockIdx.x * blockDim.x + threadIdx.x;
    int n = gt >> 5;
    if (n >= NN) return;
    int c = gt & 31;
    int head = c >> 3;
    int q = c & 3;                       // lane's slot in the unroll-4 group
    float adh = g_ad1[n * 4 + head];
    int beg = g_off[n], end = g_off[n + 1];
    half2 acc[4];
#pragma unroll
    for (int j = 0; j < 4; j++) acc[j] = __floats2half2_rn(0.f, 0.f);
    float den = 0.f;
    int i = beg;
    for (; i + 4 <= end; i += 4) {
        int sq = g_csr_src[i + q];
        float eq = __expf(leaky(g_as1[sq * 4 + head] + adh));
        float e0 = __shfl_sync(0xffffffffu, eq, (c & 24) + 0);
        float e1 = __shfl_sync(0xffffffffu, eq, (c & 24) + 1);
        float e2 = __shfl_sync(0xffffffffu, eq, (c & 24) + 2);
        float e3 = __shfl_sync(0xffffffffu, eq, (c & 24) + 3);
        int s0 = g_csr_src[i], s1 = g_csr_src[i + 1];
        int s2 = g_csr_src[i + 2], s3 = g_csr_src[i + 3];
        uint4 p0 = ((const uint4*)(g_h1 + s0 * H1DIM))[c];
        uint4 p1 = ((const uint4*)(g_h1 + s1 * H1DIM))[c];
        uint4 p2 = ((const uint4*)(g_h1 + s2 * H1DIM))[c];
        uint4 p3 = ((const uint4*)(g_h1 + s3 * H1DIM))[c];
        den += (e0 + e1) + (e2 + e3);
        half2 h0 = __float2half2_rn(e0), h1e = __float2half2_rn(e1);
        half2 h2e = __float2half2_rn(e2), h3e = __float2half2_rn(e3);
        acc[0] = __hfma2(h0, *(const half2*)&p0.x, acc[0]);
        acc[1] = __hfma2(h0, *(const half2*)&p0.y, acc[1]);
        acc[2] = __hfma2(h0, *(const half2*)&p0.z, acc[2]);
        acc[3] = __hfma2(h0, *(const half2*)&p0.w, acc[3]);
        acc[0] = __hfma2(h1e, *(const half2*)&p1.x, acc[0]);
        acc[1] = __hfma2(h1e, *(const half2*)&p1.y, acc[1]);
        acc[2] = __hfma2(h1e, *(const half2*)&p1.z, acc[2]);
        acc[3] = __hfma2(h1e, *(const half2*)&p1.w, acc[3]);
        acc[0] = __hfma2(h2e, *(const half2*)&p2.x, acc[0]);
        acc[1] = __hfma2(h2e, *(const half2*)&p2.y, acc[1]);
        acc[2] = __hfma2(h2e, *(const half2*)&p2.z, acc[2]);
        acc[3] = __hfma2(h2e, *(const half2*)&p2.w, acc[3]);
        acc[0] = __hfma2(h3e, *(const half2*)&p3.x, acc[0]);
        acc[1] = __hfma2(h3e, *(const half2*)&p3.y, acc[1]);
        acc[2] = __hfma2(h3e, *(const half2*)&p3.z, acc[2]);
        acc[3] = __hfma2(h3e, *(const half2*)&p3.w, acc[3]);
    }
    for (; i < end; i++) {
        int s0 = g_csr_src[i];
        float e0 = __expf(leaky(g_as1[s0 * 4 + head] + adh));
        uint4 p0 = ((const uint4*)(g_h1 + s0 * H1DIM))[c];
        den += e0;
        half2 h0 = __float2half2_rn(e0);
        acc[0] = __hfma2(h0, *(const half2*)&p0.x, acc[0]);
        acc[1] = __hfma2(h0, *(const half2*)&p0.y, acc[1]);
        acc[2] = __hfma2(h0, *(const half2*)&p0.z, acc[2]);
        acc[3] = __hfma2(h0, *(const half2*)&p0.w, acc[3]);
    }
    float inv = __fdividef(1.0f, den);
    float4 ba = ((const float4*)b1)[c * 2];
    float4 bb = ((const float4*)b1)[c * 2 + 1];
    float2 f0 = __half22float2(acc[0]);
    float2 f1 = __half22float2(acc[1]);
    float2 f2 = __half22float2(acc[2]);
    float2 f3 = __half22float2(acc[3]);
    half2 o0 = __floats2half2_rn(fmaxf(fmaf(f0.x, inv, ba.x), 0.f), fmaxf(fmaf(f0.y, inv, ba.y), 0.f));
    half2 o1 = __floats2half2_rn(fmaxf(fmaf(f1.x, inv, ba.z), 0.f), fmaxf(fmaf(f1.y, inv, ba.w), 0.f));
    half2 o2 = __floats2half2_rn(fmaxf(fmaf(f2.x, inv, bb.x), 0.f), fmaxf(fmaf(f2.y, inv, bb.y), 0.f));
    half2 o3 = __floats2half2_rn(fmaxf(fmaf(f3.x, inv, bb.z), 0.f), fmaxf(fmaf(f3.y, inv, bb.w), 0.f));
    uint4 pk;
    pk.x = *(unsigned*)&o0; pk.y = *(unsigned*)&o1; pk.z = *(unsigned*)&o2; pk.w = *(unsigned*)&o3;
    ((uint4*)(g_out1h + n * H1DIM))[c] = pk;
}

// ---------------- GEMM2 (HMMA) + alpha2 ----------------
__global__ __launch_bounds__(256) void gemm2_mma(const float* __restrict__ a2s,
                                                 const float* __restrict__ a2d) {
    __shared__ __align__(16) __half As[128][136];
    __shared__ __align__(16) __half Bs[128][40];
    int tid = threadIdx.x;
    int row0 = blockIdx.x * 128;
    int wid = tid >> 5, lane = tid & 31;
    float d[4][4];
#pragma unroll
    for (int nt = 0; nt < 4; nt++)
#pragma unroll
        for (int j = 0; j < 4; j++) d[nt][j] = 0.f;
    for (int st = 0; st < 2; st++) {
        for (int i = tid; i < 128 * 16; i += 256) {
            int r = i >> 4, c8 = i & 15;
            int row = row0 + r;
            uint4 v = (row < NN) ? *(const uint4*)&g_out1h[row * H1DIM + st * 128 + c8 * 8]
                                 : make_uint4(0u, 0u, 0u, 0u);
            *(uint4*)&As[r][c8 * 8] = v;
        }
        for (int i = tid; i < 128 * 4; i += 256) {
            int r = i >> 2, c8 = i & 3;
            *(uint4*)&Bs[r][c8 * 8] = *(const uint4*)&g_w2h[(st * 128 + r) * H2DIM + c8 * 8];
        }
        __syncthreads();
#pragma unroll
        for (int ks = 0; ks < 8; ks++) {
            unsigned a[4];
            unsigned aaddr = smem_u32(&As[wid * 16 + (lane & 15)][ks * 16 + (lane >> 4) * 8]);
            ldsm_x4(a[0], a[1], a[2], a[3], aaddr);
#pragma unroll
            for (int np = 0; np < 2; np++) {
                unsigned b0, b1, b2, b3;
                unsigned baddr = smem_u32(&Bs[ks * 16 + (lane & 15)][np * 16 + (lane >> 4) * 8]);
                ldsm_x4t(b0, b1, b2, b3, baddr);
                mma16816(d[np * 2], a, b0, b1);
                mma16816(d[np * 2 + 1], a, b2, b3);
            }
        }
        __syncthreads();
    }
    int g = lane >> 2, t = lane & 3;
    int r_lo = row0 + wid * 16 + g;
    int r_hi = r_lo + 8;
    float ps_lo = 0, pd_lo = 0, ps_hi = 0, pd_hi = 0;
#pragma unroll
    for (int nt = 0; nt < 4; nt++) {
        int col = nt * 8 + 2 * t;
        float s0 = a2s[col], s1 = a2s[col + 1];
        float t0 = a2d[col], t1 = a2d[col + 1];
        if (r_lo < NN) *(half2*)&g_h2[r_lo * H2DIM + col] = __floats2half2_rn(d[nt][0], d[nt][1]);
        if (r_hi < NN) *(half2*)&g_h2[r_hi * H2DIM + col] = __floats2half2_rn(d[nt][2], d[nt][3]);
        ps_lo += d[nt][0] * s0 + d[nt][1] * s1;
        pd_lo += d[nt][0] * t0 + d[nt][1] * t1;
        ps_hi += d[nt][2] * s0 + d[nt][3] * s1;
        pd_hi += d[nt][2] * t0 + d[nt][3] * t1;
    }
#pragma unroll
    for (int off = 1; off <= 2; off <<= 1) {
        ps_lo += __shfl_xor_sync(0xffffffffu, ps_lo, off);
        pd_lo += __shfl_xor_sync(0xffffffffu, pd_lo, off);
        ps_hi += __shfl_xor_sync(0xffffffffu, ps_hi, off);
        pd_hi += __shfl_xor_sync(0xffffffffu, pd_hi, off);
    }
    if (t == 0) {
        if (r_lo < NN) { g_as2[r_lo] = ps_lo; g_ad2[r_lo] = pd_lo; }
        if (r_hi < NN) { g_as2[r_hi] = ps_hi; g_ad2[r_hi] = pd_hi; }
    }
}

// ---------------- agg2 + bias + log_softmax + pool + (last block: final) ----------------
__global__ void agg2_lsm_kernel(const float* __restrict__ b2, const int* __restrict__ batch,
                                const float* __restrict__ lin_W, const float* __restrict__ lin_b,
                                float* __restrict__ out) {
    __shared__ int amLast;
    int tid = threadIdx.x;
    int gt = blockIdx.x * blockDim.x + tid;
    int n = gt >> 4;
    if (n < NN) {
        int sub = gt & 15;
        float ad = g_ad2[n];
        int beg = g_off[n], end = g_off[n + 1];
        half2 acc = __floats2half2_rn(0.f, 0.f);
        float den = 0.f;
        int i = beg;
        for (; i + 4 <= end; i += 4) {
            int s0 = g_csr_src[i], s1 = g_csr_src[i + 1];
            int s2 = g_csr_src[i + 2], s3 = g_csr_src[i + 3];
            float e0 = __expf(leaky(g_as2[s0] + ad));
            float e1 = __expf(leaky(g_as2[s1] + ad));
            float e2 = __expf(leaky(g_as2[s2] + ad));
            float e3 = __expf(leaky(g_as2[s3] + ad));
            half2 f0 = ((const half2*)(g_h2 + s0 * H2DIM))[sub];
            half2 f1 = ((const half2*)(g_h2 + s1 * H2DIM))[sub];
            half2 f2 = ((const half2*)(g_h2 + s2 * H2DIM))[sub];
            half2 f3 = ((const half2*)(g_h2 + s3 * H2DIM))[sub];
            den += (e0 + e1) + (e2 + e3);
            acc = __hfma2(__float2half2_rn(e0), f0, acc);
            acc = __hfma2(__float2half2_rn(e1), f1, acc);
            acc = __hfma2(__float2half2_rn(e2), f2, acc);
            acc = __hfma2(__float2half2_rn(e3), f3, acc);
        }
        for (; i < end; i++) {
            int s0 = g_csr_src[i];
            float e0 = __expf(leaky(g_as2[s0] + ad));
            half2 f0 = ((const half2*)(g_h2 + s0 * H2DIM))[sub];
            den += e0;
            acc = __hfma2(__float2half2_rn(e0), f0, acc);
        }
        float2 fa = __half22float2(acc);
        float inv = __fdividef(1.0f, den);
        float v0 = fmaf(fa.x, inv, b2[sub * 2]);
        float v1 = fmaf(fa.y, inv, b2[sub * 2 + 1]);
        float mx = fmaxf(v0, v1);
#pragma unroll
        for (int off = 8; off; off >>= 1) mx = fmaxf(mx, __shfl_xor_sync(0xffffffffu, mx, off));
        float s = expf(v0 - mx) + expf(v1 - mx);
#pragma unroll
        for (int off = 8; off; off >>= 1) s += __shfl_xor_sync(0xffffffffu, s, off);
        float lse = mx + logf(s);
        int b = batch[n];
        atomicAdd(&g_pool[b * H2DIM + sub * 2], v0 - lse);
        atomicAdd(&g_pool[b * H2DIM + sub * 2 + 1], v1 - lse);
        if (sub == 0) atomicAdd(&g_cnt[b], 1.0f);
    }
    __syncthreads();
    if (tid == 0) {
        __threadfence();
        int old = atomicAdd(&g_done, 1);
        amLast = (old == gridDim.x - 1) ? 1 : 0;
    }
    __syncthreads();
    if (amLast) {
        __threadfence();
        if (tid < GG) {
            float invc = 1.0f / fmaxf(g_cnt[tid], 1.0f);
            float acc2 = lin_b[0];
#pragma unroll
            for (int j = 0; j < H2DIM; j++) acc2 += g_pool[tid * H2DIM + j] * invc * lin_W[j];
            out[tid] = acc2;
        }
        if (tid == 0) g_done = 0;
    }
}

// ---------------- launcher ----------------
extern "C" void kernel_launch(void* const* d_in, const int* in_sizes, int n_in,
                              void* d_out, int out_size) {
    const float* x      = (const float*)d_in[0];
    const int*   adj    = (const int*)d_in[1];
    const int*   batch  = (const int*)d_in[2];
    const float* W1     = (const float*)d_in[3];
    const float* a1_src = (const float*)d_in[4];
    const float* a1_dst = (const float*)d_in[5];
    const float* b1     = (const float*)d_in[6];
    const float* W2     = (const float*)d_in[7];
    const float* a2_src = (const float*)d_in[8];
    const float* a2_dst = (const float*)d_in[9];
    const float* b2     = (const float*)d_in[10];
    const float* lin_W  = (const float*)d_in[11];
    const float* lin_b  = (const float*)d_in[12];
    float* out = (float*)d_out;

    const int TB = 256;

    prep_hist_kernel<<<EB + 4, TB>>>(adj, W1, a1_src, a1_dst, W2);
    scan_kernel<<<1, 1024>>>();
    mid_kernel<<<4 * EB, TB>>>(adj, x);   // scatter + gemm1 + alpha1 striped
    agg1_kernel<<<(NN * 32 + TB - 1) / TB, TB>>>(b1);
    gemm2_mma<<<(NN + 127) / 128, TB>>>(a2_src, a2_dst);
    agg2_lsm_kernel<<<AGG2B, TB>>>(b2, batch, lin_W, lin_b, out);
}

// round 17
// speedup vs baseline: 1.4966x; 1.1860x over previous
#include <cuda_runtime.h>
#include <cuda_fp16.h>
#include <math.h>

#define NN 50000
#define EE 800000
#define ET (EE + NN)
#define GG 64
#define F_IN 128
#define H1DIM 256   // HEADS * HID
#define H2DIM 32
#define NEG_SLOPE 0.2f
#define EB 3321                 // ceil(ET/256)
#define G1B 3128                // gemm1 blocks: 782 row-blocks x 4 col-blocks(=heads)
#define AGG2B 3125              // agg2 blocks

// ---------------- scratch ----------------
__device__ __align__(16) __half g_h1[NN * H1DIM];     // fp16 layer1 features
__device__ __align__(16) __half g_out1h[NN * H1DIM];  // fp16 layer1 output (gemm2 input)
__device__ __align__(16) float g_as1[NN * 4];
__device__ __align__(16) float g_ad1[NN * 4];
__device__ __align__(16) __half g_h2[NN * H2DIM];     // fp16 layer2 features
__device__ float g_as2[NN];
__device__ float g_ad2[NN];
__device__ float g_pool[GG * H2DIM];
__device__ float g_cnt[GG];
__device__ int g_deg[NN];
__device__ int g_cur[NN];
__device__ int g_off[NN + 1];
__device__ int g_csr_src[ET];
__device__ __align__(16) __half g_w2h[H1DIM * H2DIM]; // fp16 W2
__device__ int g_done;                                // agg2 last-block counter (zero-init)

// ---------------- helpers ----------------
__device__ __forceinline__ float leaky(float e) {
    return (e >= 0.f) ? e : NEG_SLOPE * e;
}
__device__ __forceinline__ unsigned smem_u32(const void* p) {
    return (unsigned)__cvta_generic_to_shared(p);
}
__device__ __forceinline__ void ldsm_x4(unsigned& r0, unsigned& r1, unsigned& r2, unsigned& r3, unsigned a) {
    asm volatile("ldmatrix.sync.aligned.m8n8.x4.shared.b16 {%0,%1,%2,%3},[%4];"
                 : "=r"(r0), "=r"(r1), "=r"(r2), "=r"(r3) : "r"(a));
}
__device__ __forceinline__ void ldsm_x4t(unsigned& r0, unsigned& r1, unsigned& r2, unsigned& r3, unsigned a) {
    asm volatile("ldmatrix.sync.aligned.m8n8.x4.trans.shared.b16 {%0,%1,%2,%3},[%4];"
                 : "=r"(r0), "=r"(r1), "=r"(r2), "=r"(r3) : "r"(a));
}
__device__ __forceinline__ void mma16816(float* d, const unsigned* a, unsigned b0, unsigned b1) {
    asm volatile("mma.sync.aligned.m16n8k16.row.col.f32.f16.f16.f32 "
                 "{%0,%1,%2,%3},{%4,%5,%6,%7},{%8,%9},{%0,%1,%2,%3};"
                 : "+f"(d[0]), "+f"(d[1]), "+f"(d[2]), "+f"(d[3])
                 : "r"(a[0]), "r"(a[1]), "r"(a[2]), "r"(a[3]), "r"(b0), "r"(b1));
}

// ---------------- K1: prep-lite (1 block) + hist (EB blocks) ----------------
__global__ void prep_hist_kernel(const int* __restrict__ adj, const float* __restrict__ W2) {
    int bx = blockIdx.x;
    int tid = threadIdx.x;
    if (bx < EB) {
        int e = bx * 256 + tid;
        if (e >= ET) return;
        int dst = (e < EE) ? adj[EE + e] : e - EE;
        atomicAdd(&g_deg[dst], 1);
    } else {
        for (int j = tid; j < H1DIM * H2DIM; j += 256) g_w2h[j] = __float2half_rn(W2[j]);
        for (int j = tid; j < GG * H2DIM; j += 256) g_pool[j] = 0.f;
        if (tid < GG) g_cnt[tid] = 0.f;
    }
}

// ---------------- K2: coalesced block scan (1024 threads) ----------------
__global__ void scan_kernel() {
    __shared__ int warpsum[32];
    int tid = threadIdx.x;
    int lane = tid & 31, wid = tid >> 5;
    int running = 0;
    for (int base = 0; base < NN; base += 1024) {
        int i = base + tid;
        int v = (i < NN) ? g_deg[i] : 0;
        int val = v;
#pragma unroll
        for (int off = 1; off < 32; off <<= 1) {
            int t = __shfl_up_sync(0xffffffffu, val, off);
            if (lane >= off) val += t;
        }
        if (lane == 31) warpsum[wid] = val;
        __syncthreads();
        if (wid == 0) {
            int s = warpsum[lane];
#pragma unroll
            for (int off = 1; off < 32; off <<= 1) {
                int t = __shfl_up_sync(0xffffffffu, s, off);
                if (lane >= off) s += t;
            }
            warpsum[lane] = s;
        }
        __syncthreads();
        int warpbase = (wid == 0) ? 0 : warpsum[wid - 1];
        int excl = running + warpbase + val - v;
        if (i < NN) { g_off[i] = excl; g_cur[i] = excl; }
        running += warpsum[31];
        __syncthreads();
    }
    if (tid == 0) g_off[NN] = running;
}

// ---------------- scatter body ----------------
__device__ void scatter_body(int base, const int* __restrict__ adj) {
    int tid = threadIdx.x;
    int gt = base * 256 + tid;
    const int STR = EB * 256;
    for (int j = gt; j < NN; j += STR) g_deg[j] = 0;   // reset for next replay
    if (gt >= ET) return;
    int src, dst;
    if (gt < EE) { src = adj[gt]; dst = adj[EE + gt]; }
    else         { src = dst = gt - EE; }
    int p = atomicAdd(&g_cur[dst], 1);
    g_csr_src[p] = src;
}

// ---------------- K3: scatter + gemm1(HMMA, fused alpha1), 2-way striped ----------------
__global__ __launch_bounds__(256) void mid_kernel(const int* __restrict__ adj,
                                                  const float* __restrict__ x,
                                                  const float* __restrict__ W1,
                                                  const float* __restrict__ a1s,
                                                  const float* __restrict__ a1d) {
    __shared__ __align__(16) __half As[64][136];
    __shared__ __align__(16) __half Bs[128][72];
    __shared__ float ps_s[64], pd_s[64];
    int m = blockIdx.x & 1, base = blockIdx.x >> 1;
    if (m) { if (base < EB) scatter_body(base, adj); return; }
    if (base >= G1B) return;
    int tid = threadIdx.x;
    int row0 = (base >> 2) * 64;
    int hd = base & 3;              // head = col-block
    int col0 = hd * 64;
    // A: 64x128 fp32 -> fp16
    for (int i = tid; i < 64 * 32; i += 256) {
        int r = i >> 5, c4 = i & 31;
        int row = row0 + r;
        float4 v = (row < NN) ? *(const float4*)&x[row * F_IN + c4 * 4]
                              : make_float4(0.f, 0.f, 0.f, 0.f);
        *(half2*)&As[r][c4 * 4] = __floats2half2_rn(v.x, v.y);
        *(half2*)&As[r][c4 * 4 + 2] = __floats2half2_rn(v.z, v.w);
    }
    // B: 128x64 fp32 W1 slice -> fp16 via float2
    for (int i = tid; i < 128 * 32; i += 256) {
        int r = i >> 5, c2 = i & 31;
        float2 v = *(const float2*)&W1[r * H1DIM + col0 + c2 * 2];
        *(half2*)&Bs[r][c2 * 2] = __floats2half2_rn(v.x, v.y);
    }
    __syncthreads();
    int wid = tid >> 5, lane = tid & 31;
    int rowg = wid >> 1, colg = wid & 1;
    unsigned a[8][4];
#pragma unroll
    for (int ks = 0; ks < 8; ks++) {
        unsigned addr = smem_u32(&As[rowg * 16 + (lane & 15)][ks * 16 + (lane >> 4) * 8]);
        ldsm_x4(a[ks][0], a[ks][1], a[ks][2], a[ks][3], addr);
    }
    float d[4][4];
#pragma unroll
    for (int nt = 0; nt < 4; nt++)
#pragma unroll
        for (int j = 0; j < 4; j++) d[nt][j] = 0.f;
#pragma unroll
    for (int np = 0; np < 2; np++) {
#pragma unroll
        for (int ks = 0; ks < 8; ks++) {
            unsigned b0, b1, b2, b3;
            unsigned addr = smem_u32(&Bs[ks * 16 + (lane & 15)][colg * 32 + np * 16 + (lane >> 4) * 8]);
            ldsm_x4t(b0, b1, b2, b3, addr);
            mma16816(d[np * 2], a[ks], b0, b1);
            mma16816(d[np * 2 + 1], a[ks], b2, b3);
        }
    }
    int g = lane >> 2, t = lane & 3;
    int r_lo = row0 + rowg * 16 + g;
    int r_hi = r_lo + 8;
    // store h1 + accumulate alpha partials
    float ps_lo = 0, pd_lo = 0, ps_hi = 0, pd_hi = 0;
#pragma unroll
    for (int nt = 0; nt < 4; nt++) {
        int cl = colg * 32 + nt * 8 + 2 * t;       // local col within head
        int col = col0 + cl;
        float s0 = a1s[col], s1 = a1s[col + 1];
        float t0 = a1d[col], t1 = a1d[col + 1];
        if (r_lo < NN) *(half2*)&g_h1[r_lo * H1DIM + col] = __floats2half2_rn(d[nt][0], d[nt][1]);
        if (r_hi < NN) *(half2*)&g_h1[r_hi * H1DIM + col] = __floats2half2_rn(d[nt][2], d[nt][3]);
        ps_lo += d[nt][0] * s0 + d[nt][1] * s1;
        pd_lo += d[nt][0] * t0 + d[nt][1] * t1;
        ps_hi += d[nt][2] * s0 + d[nt][3] * s1;
        pd_hi += d[nt][2] * t0 + d[nt][3] * t1;
    }
#pragma unroll
    for (int off = 1; off <= 2; off <<= 1) {
        ps_lo += __shfl_xor_sync(0xffffffffu, ps_lo, off);
        pd_lo += __shfl_xor_sync(0xffffffffu, pd_lo, off);
        ps_hi += __shfl_xor_sync(0xffffffffu, ps_hi, off);
        pd_hi += __shfl_xor_sync(0xffffffffu, pd_hi, off);
    }
    int rl = rowg * 16 + g;
    if (t == 0 && colg == 0) {
        ps_s[rl] = ps_lo; pd_s[rl] = pd_lo;
        ps_s[rl + 8] = ps_hi; pd_s[rl + 8] = pd_hi;
    }
    __syncthreads();
    if (t == 0 && colg == 1) {
        if (r_lo < NN) {
            g_as1[r_lo * 4 + hd] = ps_s[rl] + ps_lo;
            g_ad1[r_lo * 4 + hd] = pd_s[rl] + pd_lo;
        }
        if (r_hi < NN) {
            g_as1[r_hi * 4 + hd] = ps_s[rl + 8] + ps_hi;
            g_ad1[r_hi * 4 + hd] = pd_s[rl + 8] + pd_hi;
        }
    }
}

// ---------------- agg1: 32 threads/node, shuffle-split exp, HFMA2 accumulation ----------------
__global__ void agg1_kernel(const float* __restrict__ b1) {
    int gt = blockIdx.x * blockDim.x + threadIdx.x;
    int n = gt >> 5;
    if (n >= NN) return;
    int c = gt & 31;
    int head = c >> 3;
    int q = c & 3;
    float adh = g_ad1[n * 4 + head];
    int beg = g_off[n], end = g_off[n + 1];
    half2 acc[4];
#pragma unroll
    for (int j = 0; j < 4; j++) acc[j] = __floats2half2_rn(0.f, 0.f);
    float den = 0.f;
    int i = beg;
    for (; i + 4 <= end; i += 4) {
        int sq = g_csr_src[i + q];
        float eq = __expf(leaky(g_as1[sq * 4 + head] + adh));
        float e0 = __shfl_sync(0xffffffffu, eq, (c & 24) + 0);
        float e1 = __shfl_sync(0xffffffffu, eq, (c & 24) + 1);
        float e2 = __shfl_sync(0xffffffffu, eq, (c & 24) + 2);
        float e3 = __shfl_sync(0xffffffffu, eq, (c & 24) + 3);
        int s0 = g_csr_src[i], s1 = g_csr_src[i + 1];
        int s2 = g_csr_src[i + 2], s3 = g_csr_src[i + 3];
        uint4 p0 = ((const uint4*)(g_h1 + s0 * H1DIM))[c];
        uint4 p1 = ((const uint4*)(g_h1 + s1 * H1DIM))[c];
        uint4 p2 = ((const uint4*)(g_h1 + s2 * H1DIM))[c];
        uint4 p3 = ((const uint4*)(g_h1 + s3 * H1DIM))[c];
        den += (e0 + e1) + (e2 + e3);
        half2 h0 = __float2half2_rn(e0), h1e = __float2half2_rn(e1);
        half2 h2e = __float2half2_rn(e2), h3e = __float2half2_rn(e3);
        acc[0] = __hfma2(h0, *(const half2*)&p0.x, acc[0]);
        acc[1] = __hfma2(h0, *(const half2*)&p0.y, acc[1]);
        acc[2] = __hfma2(h0, *(const half2*)&p0.z, acc[2]);
        acc[3] = __hfma2(h0, *(const half2*)&p0.w, acc[3]);
        acc[0] = __hfma2(h1e, *(const half2*)&p1.x, acc[0]);
        acc[1] = __hfma2(h1e, *(const half2*)&p1.y, acc[1]);
        acc[2] = __hfma2(h1e, *(const half2*)&p1.z, acc[2]);
        acc[3] = __hfma2(h1e, *(const half2*)&p1.w, acc[3]);
        acc[0] = __hfma2(h2e, *(const half2*)&p2.x, acc[0]);
        acc[1] = __hfma2(h2e, *(const half2*)&p2.y, acc[1]);
        acc[2] = __hfma2(h2e, *(const half2*)&p2.z, acc[2]);
        acc[3] = __hfma2(h2e, *(const half2*)&p2.w, acc[3]);
        acc[0] = __hfma2(h3e, *(const half2*)&p3.x, acc[0]);
        acc[1] = __hfma2(h3e, *(const half2*)&p3.y, acc[1]);
        acc[2] = __hfma2(h3e, *(const half2*)&p3.z, acc[2]);
        acc[3] = __hfma2(h3e, *(const half2*)&p3.w, acc[3]);
    }
    for (; i < end; i++) {
        int s0 = g_csr_src[i];
        float e0 = __expf(leaky(g_as1[s0 * 4 + head] + adh));
        uint4 p0 = ((const uint4*)(g_h1 + s0 * H1DIM))[c];
        den += e0;
        half2 h0 = __float2half2_rn(e0);
        acc[0] = __hfma2(h0, *(const half2*)&p0.x, acc[0]);
        acc[1] = __hfma2(h0, *(const half2*)&p0.y, acc[1]);
        acc[2] = __hfma2(h0, *(const half2*)&p0.z, acc[2]);
        acc[3] = __hfma2(h0, *(const half2*)&p0.w, acc[3]);
    }
    float inv = __fdividef(1.0f, den);
    float4 ba = ((const float4*)b1)[c * 2];
    float4 bb = ((const float4*)b1)[c * 2 + 1];
    float2 f0 = __half22float2(acc[0]);
    float2 f1 = __half22float2(acc[1]);
    float2 f2 = __half22float2(acc[2]);
    float2 f3 = __half22float2(acc[3]);
    half2 o0 = __floats2half2_rn(fmaxf(fmaf(f0.x, inv, ba.x), 0.f), fmaxf(fmaf(f0.y, inv, ba.y), 0.f));
    half2 o1 = __floats2half2_rn(fmaxf(fmaf(f1.x, inv, ba.z), 0.f), fmaxf(fmaf(f1.y, inv, ba.w), 0.f));
    half2 o2 = __floats2half2_rn(fmaxf(fmaf(f2.x, inv, bb.x), 0.f), fmaxf(fmaf(f2.y, inv, bb.y), 0.f));
    half2 o3 = __floats2half2_rn(fmaxf(fmaf(f3.x, inv, bb.z), 0.f), fmaxf(fmaf(f3.y, inv, bb.w), 0.f));
    uint4 pk;
    pk.x = *(unsigned*)&o0; pk.y = *(unsigned*)&o1; pk.z = *(unsigned*)&o2; pk.w = *(unsigned*)&o3;
    ((uint4*)(g_out1h + n * H1DIM))[c] = pk;
}

// ---------------- GEMM2 (HMMA) + alpha2 ----------------
__global__ __launch_bounds__(256) void gemm2_mma(const float* __restrict__ a2s,
                                                 const float* __restrict__ a2d) {
    __shared__ __align__(16) __half As[128][136];
    __shared__ __align__(16) __half Bs[128][40];
    int tid = threadIdx.x;
    int row0 = blockIdx.x * 128;
    int wid = tid >> 5, lane = tid & 31;
    float d[4][4];
#pragma unroll
    for (int nt = 0; nt < 4; nt++)
#pragma unroll
        for (int j = 0; j < 4; j++) d[nt][j] = 0.f;
    for (int st = 0; st < 2; st++) {
        for (int i = tid; i < 128 * 16; i += 256) {
            int r = i >> 4, c8 = i & 15;
            int row = row0 + r;
            uint4 v = (row < NN) ? *(const uint4*)&g_out1h[row * H1DIM + st * 128 + c8 * 8]
                                 : make_uint4(0u, 0u, 0u, 0u);
            *(uint4*)&As[r][c8 * 8] = v;
        }
        for (int i = tid; i < 128 * 4; i += 256) {
            int r = i >> 2, c8 = i & 3;
            *(uint4*)&Bs[r][c8 * 8] = *(const uint4*)&g_w2h[(st * 128 + r) * H2DIM + c8 * 8];
        }
        __syncthreads();
#pragma unroll
        for (int ks = 0; ks < 8; ks++) {
            unsigned a[4];
            unsigned aaddr = smem_u32(&As[wid * 16 + (lane & 15)][ks * 16 + (lane >> 4) * 8]);
            ldsm_x4(a[0], a[1], a[2], a[3], aaddr);
#pragma unroll
            for (int np = 0; np < 2; np++) {
                unsigned b0, b1, b2, b3;
                unsigned baddr = smem_u32(&Bs[ks * 16 + (lane & 15)][np * 16 + (lane >> 4) * 8]);
                ldsm_x4t(b0, b1, b2, b3, baddr);
                mma16816(d[np * 2], a, b0, b1);
                mma16816(d[np * 2 + 1], a, b2, b3);
            }
        }
        __syncthreads();
    }
    int g = lane >> 2, t = lane & 3;
    int r_lo = row0 + wid * 16 + g;
    int r_hi = r_lo + 8;
    float ps_lo = 0, pd_lo = 0, ps_hi = 0, pd_hi = 0;
#pragma unroll
    for (int nt = 0; nt < 4; nt++) {
        int col = nt * 8 + 2 * t;
        float s0 = a2s[col], s1 = a2s[col + 1];
        float t0 = a2d[col], t1 = a2d[col + 1];
        if (r_lo < NN) *(half2*)&g_h2[r_lo * H2DIM + col] = __floats2half2_rn(d[nt][0], d[nt][1]);
        if (r_hi < NN) *(half2*)&g_h2[r_hi * H2DIM + col] = __floats2half2_rn(d[nt][2], d[nt][3]);
        ps_lo += d[nt][0] * s0 + d[nt][1] * s1;
        pd_lo += d[nt][0] * t0 + d[nt][1] * t1;
        ps_hi += d[nt][2] * s0 + d[nt][3] * s1;
        pd_hi += d[nt][2] * t0 + d[nt][3] * t1;
    }
#pragma unroll
    for (int off = 1; off <= 2; off <<= 1) {
        ps_lo += __shfl_xor_sync(0xffffffffu, ps_lo, off);
        pd_lo += __shfl_xor_sync(0xffffffffu, pd_lo, off);
        ps_hi += __shfl_xor_sync(0xffffffffu, ps_hi, off);
        pd_hi += __shfl_xor_sync(0xffffffffu, pd_hi, off);
    }
    if (t == 0) {
        if (r_lo < NN) { g_as2[r_lo] = ps_lo; g_ad2[r_lo] = pd_lo; }
        if (r_hi < NN) { g_as2[r_hi] = ps_hi; g_ad2[r_hi] = pd_hi; }
    }
}

// ---------------- agg2 + bias + log_softmax + pool + (last block: final) ----------------
// R14-proven body: per-lane exp, 16 threads/node, no cross-node shuffles in the loop
__global__ void agg2_lsm_kernel(const float* __restrict__ b2, const int* __restrict__ batch,
                                const float* __restrict__ lin_W, const float* __restrict__ lin_b,
                                float* __restrict__ out) {
    __shared__ int amLast;
    int tid = threadIdx.x;
    int gt = blockIdx.x * blockDim.x + tid;
    int n = gt >> 4;
    if (n < NN) {
        int sub = gt & 15;
        float ad = g_ad2[n];
        int beg = g_off[n], end = g_off[n + 1];
        half2 acc = __floats2half2_rn(0.f, 0.f);
        float den = 0.f;
        int i = beg;
        for (; i + 4 <= end; i += 4) {
            int s0 = g_csr_src[i], s1 = g_csr_src[i + 1];
            int s2 = g_csr_src[i + 2], s3 = g_csr_src[i + 3];
            float e0 = __expf(leaky(g_as2[s0] + ad));
            float e1 = __expf(leaky(g_as2[s1] + ad));
            float e2 = __expf(leaky(g_as2[s2] + ad));
            float e3 = __expf(leaky(g_as2[s3] + ad));
            half2 f0 = ((const half2*)(g_h2 + s0 * H2DIM))[sub];
            half2 f1 = ((const half2*)(g_h2 + s1 * H2DIM))[sub];
            half2 f2 = ((const half2*)(g_h2 + s2 * H2DIM))[sub];
            half2 f3 = ((const half2*)(g_h2 + s3 * H2DIM))[sub];
            den += (e0 + e1) + (e2 + e3);
            acc = __hfma2(__float2half2_rn(e0), f0, acc);
            acc = __hfma2(__float2half2_rn(e1), f1, acc);
            acc = __hfma2(__float2half2_rn(e2), f2, acc);
            acc = __hfma2(__float2half2_rn(e3), f3, acc);
        }
        for (; i < end; i++) {
            int s0 = g_csr_src[i];
            float e0 = __expf(leaky(g_as2[s0] + ad));
            half2 f0 = ((const half2*)(g_h2 + s0 * H2DIM))[sub];
            den += e0;
            acc = __hfma2(__float2half2_rn(e0), f0, acc);
        }
        float2 fa = __half22float2(acc);
        float inv = __fdividef(1.0f, den);
        float v0 = fmaf(fa.x, inv, b2[sub * 2]);
        float v1 = fmaf(fa.y, inv, b2[sub * 2 + 1]);
        float mx = fmaxf(v0, v1);
#pragma unroll
        for (int off = 8; off; off >>= 1) mx = fmaxf(mx, __shfl_xor_sync(0xffffffffu, mx, off));
        float s = expf(v0 - mx) + expf(v1 - mx);
#pragma unroll
        for (int off = 8; off; off >>= 1) s += __shfl_xor_sync(0xffffffffu, s, off);
        float lse = mx + logf(s);
        int b = batch[n];
        atomicAdd(&g_pool[b * H2DIM + sub * 2], v0 - lse);
        atomicAdd(&g_pool[b * H2DIM + sub * 2 + 1], v1 - lse);
        if (sub == 0) atomicAdd(&g_cnt[b], 1.0f);
    }
    __syncthreads();
    if (tid == 0) {
        __threadfence();
        int old = atomicAdd(&g_done, 1);
        amLast = (old == gridDim.x - 1) ? 1 : 0;
    }
    __syncthreads();
    if (amLast) {
        __threadfence();
        if (tid < GG) {
            float invc = 1.0f / fmaxf(g_cnt[tid], 1.0f);
            float acc2 = lin_b[0];
#pragma unroll
            for (int j = 0; j < H2DIM; j++) acc2 += g_pool[tid * H2DIM + j] * invc * lin_W[j];
            out[tid] = acc2;
        }
        if (tid == 0) g_done = 0;
    }
}

// ---------------- launcher ----------------
extern "C" void kernel_launch(void* const* d_in, const int* in_sizes, int n_in,
                              void* d_out, int out_size) {
    const float* x      = (const float*)d_in[0];
    const int*   adj    = (const int*)d_in[1];
    const int*   batch  = (const int*)d_in[2];
    const float* W1     = (const float*)d_in[3];
    const float* a1_src = (const float*)d_in[4];
    const float* a1_dst = (const float*)d_in[5];
    const float* b1     = (const float*)d_in[6];
    const float* W2     = (const float*)d_in[7];
    const float* a2_src = (const float*)d_in[8];
    const float* a2_dst = (const float*)d_in[9];
    const float* b2     = (const float*)d_in[10];
    const float* lin_W  = (const float*)d_in[11];
    const float* lin_b  = (const float*)d_in[12];
    float* out = (float*)d_out;

    const int TB = 256;

    prep_hist_kernel<<<EB + 1, TB>>>(adj, W2);
    scan_kernel<<<1, 1024>>>();
    mid_kernel<<<2 * EB, TB>>>(adj, x, W1, a1_src, a1_dst);   // scatter + gemm1(+alpha1)
    agg1_kernel<<<(NN * 32 + TB - 1) / TB, TB>>>(b1);
    gemm2_mma<<<(NN + 127) / 128, TB>>>(a2_src, a2_dst);
    agg2_lsm_kernel<<<AGG2B, TB>>>(b2, batch, lin_W, lin_b, out);
}